// round 1
// baseline (speedup 1.0000x reference)
#include <cuda_runtime.h>
#include <math.h>

// ---------------------------------------------------------------------------
// Problem constants: n=4, C=128, H=W=64, K_SIZE=5 (K2=25), N_HEAD=4, d=32
// Inputs (metadata order): q, k, v, flow, Wq, Wk, Wv, Wfc
// Output: concat( out[4,128,64,64], attn[4,4,25,64,64] )  -- 3,735,552 f32
// ---------------------------------------------------------------------------

#define NB      4
#define CC      128
#define HH      64
#define WW      64
#define HW      4096            // 64*64
#define NPIX    (NB*HW)         // 16384
#define PLANE   (CC*HW)         // 524288 per batch
#define K2      25
#define NHEAD   4
#define DHEAD   32

// Scratch (device globals: no allocation allowed in kernel_launch)
__device__ float g_qp[NB*HW*CC];    // NHWC, pre-scaled by 1/sqrt(d)
__device__ float g_kp[NB*HW*CC];    // NHWC
__device__ float g_vp[NB*HW*CC];    // NHWC
__device__ float g_opre[NB*HW*CC];  // NHWC attention output (pre-Wfc)

// ---------------------------------------------------------------------------
// Tiled SGEMM:  Y[o][p] = sum_k W[o][k] * X[k][p]   (per batch n)
// Block: 256 threads, tile 128(o) x 128(p), k-tiles of 8, 8x8 microtile.
// XMODE 0: X is [k][p] (NCHW input),  XMODE 1: X is [p][k] (NHWC scratch)
// YMODE 0: Y is [o][p] (NCHW out),    YMODE 1: Y is [p][o] (NHWC scratch)
// ---------------------------------------------------------------------------
template<int XMODE, int YMODE>
__global__ __launch_bounds__(256)
void gemm128(const float* __restrict__ W, const float* __restrict__ X,
             float* __restrict__ Y, float scale)
{
    __shared__ float Wt[8 * 132];   // [k][o], padded stride 132 (conflict-free)
    __shared__ float Xt[8 * 132];   // [k][p], padded stride 132

    const int tid  = threadIdx.x;
    const int tx   = tid & 15;      // o-dim: 16 x 8 = 128
    const int ty   = tid >> 4;      // p-dim: 16 x 8 = 128
    const int n    = blockIdx.y;
    const int pix0 = blockIdx.x * 128;

    const float* Xn = X + (size_t)n * PLANE;
    float*       Yn = Y + (size_t)n * PLANE;

    float acc[8][8];
    #pragma unroll
    for (int p = 0; p < 8; p++)
        #pragma unroll
        for (int o = 0; o < 8; o++) acc[p][o] = 0.f;

    for (int k0 = 0; k0 < 128; k0 += 8) {
        // Load W tile transposed: Wt[k][o] = W[o*128 + k0+k]
        // global: 8 contiguous floats per row chunk -> 32B sectors, coalesced enough
        #pragma unroll
        for (int it = 0; it < 4; it++) {
            int i = tid + it * 256;          // 0..1023
            int r  = i >> 3;                 // o (0..127)
            int kc = i & 7;                  // k (0..7)
            Wt[kc * 132 + r] = W[r * 128 + k0 + kc];
        }
        if (XMODE == 0) {
            #pragma unroll
            for (int it = 0; it < 4; it++) {
                int i = tid + it * 256;
                int kc = i >> 7, p = i & 127;
                Xt[kc * 132 + p] = Xn[(size_t)(k0 + kc) * HW + pix0 + p];
            }
        } else {
            #pragma unroll
            for (int it = 0; it < 4; it++) {
                int i = tid + it * 256;
                int p = i >> 3, kc = i & 7;
                Xt[kc * 132 + p] = Xn[(size_t)(pix0 + p) * CC + k0 + kc];
            }
        }
        __syncthreads();

        #pragma unroll
        for (int kc = 0; kc < 8; kc++) {
            float4 a0 = *(const float4*)&Wt[kc * 132 + tx * 8];
            float4 a1 = *(const float4*)&Wt[kc * 132 + tx * 8 + 4];
            float a[8] = {a0.x, a0.y, a0.z, a0.w, a1.x, a1.y, a1.z, a1.w};
            float b[8];
            #pragma unroll
            for (int i = 0; i < 8; i++) b[i] = Xt[kc * 132 + ty * 8 + i];
            #pragma unroll
            for (int p = 0; p < 8; p++)
                #pragma unroll
                for (int o = 0; o < 8; o++)
                    acc[p][o] = fmaf(a[o], b[p], acc[p][o]);
        }
        __syncthreads();
    }

    if (YMODE == 1) {
        // Y[p][o] (NHWC): per pixel, 16 tx-threads cover 128 contiguous channels
        #pragma unroll
        for (int p = 0; p < 8; p++) {
            size_t base = (size_t)(pix0 + ty * 8 + p) * CC + tx * 8;
            float4 v0 = make_float4(acc[p][0] * scale, acc[p][1] * scale,
                                    acc[p][2] * scale, acc[p][3] * scale);
            float4 v1 = make_float4(acc[p][4] * scale, acc[p][5] * scale,
                                    acc[p][6] * scale, acc[p][7] * scale);
            *(float4*)&Yn[base]     = v0;
            *(float4*)&Yn[base + 4] = v1;
        }
    } else {
        // Y[o][p] (NCHW): per channel row, contiguous pixels
        #pragma unroll
        for (int o = 0; o < 8; o++) {
            size_t base = (size_t)(tx * 8 + o) * HW + pix0 + ty * 8;
            float4 v0 = make_float4(acc[0][o] * scale, acc[1][o] * scale,
                                    acc[2][o] * scale, acc[3][o] * scale);
            float4 v1 = make_float4(acc[4][o] * scale, acc[5][o] * scale,
                                    acc[6][o] * scale, acc[7][o] * scale);
            *(float4*)&Yn[base]     = v0;
            *(float4*)&Yn[base + 4] = v1;
        }
    }
}

// ---------------------------------------------------------------------------
// Attention kernel: one pixel per 128-thread block (thread = channel).
// warp w handles head w for the reductions (channels are head-major).
// All gathers hit NHWC tensors -> each bilinear tap is 512B contiguous.
// ---------------------------------------------------------------------------
__global__ __launch_bounds__(128)
void attn_kernel(const float* __restrict__ qp, const float* __restrict__ kp,
                 const float* __restrict__ vp, const float* __restrict__ flow,
                 float* __restrict__ attn_out, float* __restrict__ opre)
{
    const int pix  = blockIdx.x;
    const int n    = pix >> 12;
    const int yx   = pix & 4095;
    const int y    = yx >> 6;
    const int x    = yx & 63;
    const int c    = threadIdx.x;
    const int head = c >> 5;
    const int lane = c & 31;

    __shared__ int   s_tidx[K2][4];
    __shared__ float s_tw[K2][4];
    __shared__ float s_logit[NHEAD][32];
    __shared__ float s_attn[NHEAD][32];

    // ---- Phase 0: 25 threads compute the bilinear taps once ----
    if (c < K2) {
        const int kk = c;
        float fx = flow[(size_t)(n * 2 + 0) * HW + yx];
        float fy = flow[(size_t)(n * 2 + 1) * HW + yx];
        float sx = (float)(kk % 5 - 2);
        float sy = (float)(kk / 5 - 2);
        // replicate reference normalize->denormalize round trip exactly
        float vxn = 2.0f * ((float)x + sx + fx) / 63.0f - 1.0f;
        float vyn = 2.0f * ((float)y + sy + fy) / 63.0f - 1.0f;
        float xs = (vxn + 1.0f) * 0.5f * 63.0f;
        float ys = (vyn + 1.0f) * 0.5f * 63.0f;
        float x0f = floorf(xs), y0f = floorf(ys);
        float wx = xs - x0f,    wy = ys - y0f;
        #pragma unroll
        for (int t = 0; t < 4; t++) {
            float xi = x0f + (float)(t & 1);
            float yi = y0f + (float)(t >> 1);
            bool inb = (xi >= 0.f) && (xi <= 63.f) && (yi >= 0.f) && (yi <= 63.f);
            float wwx = (t & 1)  ? wx : 1.f - wx;
            float wwy = (t >> 1) ? wy : 1.f - wy;
            s_tidx[kk][t] = inb ? (((n << 12) + (int)yi * WW + (int)xi) * CC) : -1;
            s_tw[kk][t]   = wwx * wwy;
        }
    }
    __syncthreads();

    // ---- Phase 1: logits[head][kk] = (q/sqrt(d)) . k_sampled ----
    const float qv = qp[(size_t)pix * CC + c];   // already scaled by 1/sqrt(d)
    #pragma unroll 5
    for (int kk = 0; kk < K2; kk++) {
        float v = 0.f;
        #pragma unroll
        for (int t = 0; t < 4; t++) {
            int idx = s_tidx[kk][t];
            if (idx >= 0) v = fmaf(s_tw[kk][t], kp[idx + c], v);
        }
        float part = qv * v;
        #pragma unroll
        for (int off = 16; off; off >>= 1)
            part += __shfl_xor_sync(0xffffffffu, part, off);
        if (lane == 0) s_logit[head][kk] = part;
    }
    __syncthreads();

    // ---- Phase 2: softmax over 25 per head (warp `head`) ----
    {
        float lg = (lane < K2) ? s_logit[head][lane] : -INFINITY;
        float m = lg;
        #pragma unroll
        for (int off = 16; off; off >>= 1)
            m = fmaxf(m, __shfl_xor_sync(0xffffffffu, m, off));
        float e = (lane < K2) ? __expf(lg - m) : 0.f;
        float s = e;
        #pragma unroll
        for (int off = 16; off; off >>= 1)
            s += __shfl_xor_sync(0xffffffffu, s, off);
        float a = e / s;
        if (lane < K2) {
            s_attn[head][lane] = a;
            attn_out[(size_t)((n * NHEAD + head) * K2 + lane) * HW + yx] = a;
        }
    }
    __syncthreads();

    // ---- Phase 3: out[c] = sum_kk attn[head][kk] * v_sampled[kk][c] ----
    float acc = 0.f;
    #pragma unroll 5
    for (int kk = 0; kk < K2; kk++) {
        float v = 0.f;
        #pragma unroll
        for (int t = 0; t < 4; t++) {
            int idx = s_tidx[kk][t];
            if (idx >= 0) v = fmaf(s_tw[kk][t], vp[idx + c], v);
        }
        acc = fmaf(s_attn[head][kk], v, acc);
    }
    opre[(size_t)pix * CC + c] = acc;
}

// ---------------------------------------------------------------------------
extern "C" void kernel_launch(void* const* d_in, const int* in_sizes, int n_in,
                              void* d_out, int out_size)
{
    const float* q    = (const float*)d_in[0];
    const float* k    = (const float*)d_in[1];
    const float* v    = (const float*)d_in[2];
    const float* flow = (const float*)d_in[3];
    const float* Wq   = (const float*)d_in[4];
    const float* Wk   = (const float*)d_in[5];
    const float* Wv   = (const float*)d_in[6];
    const float* Wfc  = (const float*)d_in[7];

    float* out  = (float*)d_out;                       // [4,128,64,64]
    float* attn = out + (size_t)NB * CC * HW;          // [4,4,25,64,64]

    float *qp, *kp, *vp, *opre;
    cudaGetSymbolAddress((void**)&qp,   g_qp);
    cudaGetSymbolAddress((void**)&kp,   g_kp);
    cudaGetSymbolAddress((void**)&vp,   g_vp);
    cudaGetSymbolAddress((void**)&opre, g_opre);

    const float qscale = 0.17677669529663687f;         // 1/sqrt(32)
    dim3 gg(HW / 128, NB);                             // (32, 4)

    gemm128<0, 1><<<gg, 256>>>(Wq, q, qp, qscale);     // NCHW in -> NHWC qp
    gemm128<0, 1><<<gg, 256>>>(Wk, k, kp, 1.f);
    gemm128<0, 1><<<gg, 256>>>(Wv, v, vp, 1.f);

    attn_kernel<<<NPIX, 128>>>(qp, kp, vp, flow, attn, opre);

    gemm128<1, 0><<<gg, 256>>>(Wfc, opre, out, 1.f);   // NHWC in -> NCHW out
}

// round 2
// speedup vs baseline: 1.9384x; 1.9384x over previous
#include <cuda_runtime.h>
#include <math.h>

// ---------------------------------------------------------------------------
// n=4, C=128, H=W=64, K_SIZE=5 (K2=25), N_HEAD=4, d=32
// Inputs: q, k, v, flow, Wq, Wk, Wv, Wfc
// Output: concat( out[4,128,64,64], attn[4,4,25,64,64] )
// ---------------------------------------------------------------------------

#define NB      4
#define CC      128
#define WW      64
#define HW      4096
#define NPIX    (NB*HW)
#define PLANE   (CC*HW)
#define K2      25
#define NHEAD   4

__device__ float g_qp[NB*HW*CC];    // NHWC, pre-scaled by 1/sqrt(d)
__device__ float g_kp[NB*HW*CC];    // NHWC
__device__ float g_vp[NB*HW*CC];    // NHWC
__device__ float g_opre[NB*HW*CC];  // NHWC

// ---------------------------------------------------------------------------
// SGEMM core: Y[o][p] = sum_k W[o][k] * X[k][p] per batch (128x128x HW)
// ---------------------------------------------------------------------------
template<int XMODE, int YMODE>
__device__ __forceinline__
void gemm_core(const float* __restrict__ W, const float* __restrict__ X,
               float* __restrict__ Y, float scale)
{
    __shared__ float Wt[8 * 132];
    __shared__ float Xt[8 * 132];

    const int tid  = threadIdx.x;
    const int tx   = tid & 15;
    const int ty   = tid >> 4;
    const int n    = blockIdx.y;
    const int pix0 = blockIdx.x * 128;

    const float* Xn = X + (size_t)n * PLANE;
    float*       Yn = Y + (size_t)n * PLANE;

    float acc[8][8];
    #pragma unroll
    for (int p = 0; p < 8; p++)
        #pragma unroll
        for (int o = 0; o < 8; o++) acc[p][o] = 0.f;

    for (int k0 = 0; k0 < 128; k0 += 8) {
        #pragma unroll
        for (int it = 0; it < 4; it++) {
            int i = tid + it * 256;
            int r  = i >> 3;
            int kc = i & 7;
            Wt[kc * 132 + r] = W[r * 128 + k0 + kc];
        }
        if (XMODE == 0) {
            #pragma unroll
            for (int it = 0; it < 4; it++) {
                int i = tid + it * 256;
                int kc = i >> 7, p = i & 127;
                Xt[kc * 132 + p] = Xn[(size_t)(k0 + kc) * HW + pix0 + p];
            }
        } else {
            #pragma unroll
            for (int it = 0; it < 4; it++) {
                int i = tid + it * 256;
                int p = i >> 3, kc = i & 7;
                Xt[kc * 132 + p] = Xn[(size_t)(pix0 + p) * CC + k0 + kc];
            }
        }
        __syncthreads();

        #pragma unroll
        for (int kc = 0; kc < 8; kc++) {
            float4 a0 = *(const float4*)&Wt[kc * 132 + tx * 8];
            float4 a1 = *(const float4*)&Wt[kc * 132 + tx * 8 + 4];
            float a[8] = {a0.x, a0.y, a0.z, a0.w, a1.x, a1.y, a1.z, a1.w};
            float b[8];
            #pragma unroll
            for (int i = 0; i < 8; i++) b[i] = Xt[kc * 132 + ty * 8 + i];
            #pragma unroll
            for (int p = 0; p < 8; p++)
                #pragma unroll
                for (int o = 0; o < 8; o++)
                    acc[p][o] = fmaf(a[o], b[p], acc[p][o]);
        }
        __syncthreads();
    }

    if (YMODE == 1) {
        #pragma unroll
        for (int p = 0; p < 8; p++) {
            size_t base = (size_t)(pix0 + ty * 8 + p) * CC + tx * 8;
            float4 v0 = make_float4(acc[p][0] * scale, acc[p][1] * scale,
                                    acc[p][2] * scale, acc[p][3] * scale);
            float4 v1 = make_float4(acc[p][4] * scale, acc[p][5] * scale,
                                    acc[p][6] * scale, acc[p][7] * scale);
            *(float4*)&Yn[base]     = v0;
            *(float4*)&Yn[base + 4] = v1;
        }
    } else {
        #pragma unroll
        for (int o = 0; o < 8; o++) {
            size_t base = (size_t)(tx * 8 + o) * HW + pix0 + ty * 8;
            float4 v0 = make_float4(acc[0][o] * scale, acc[1][o] * scale,
                                    acc[2][o] * scale, acc[3][o] * scale);
            float4 v1 = make_float4(acc[4][o] * scale, acc[5][o] * scale,
                                    acc[6][o] * scale, acc[7][o] * scale);
            *(float4*)&Yn[base]     = v0;
            *(float4*)&Yn[base + 4] = v1;
        }
    }
}

// Fused q/k/v projections: blockIdx.z selects which GEMM
__global__ __launch_bounds__(256)
void gemm_qkv(const float* __restrict__ Wq, const float* __restrict__ Wk,
              const float* __restrict__ Wv,
              const float* __restrict__ q, const float* __restrict__ k,
              const float* __restrict__ v,
              float* __restrict__ qp, float* __restrict__ kp,
              float* __restrict__ vp, float qscale)
{
    const float* W; const float* X; float* Y; float s;
    if (blockIdx.z == 0)      { W = Wq; X = q; Y = qp; s = qscale; }
    else if (blockIdx.z == 1) { W = Wk; X = k; Y = kp; s = 1.f; }
    else                      { W = Wv; X = v; Y = vp; s = 1.f; }
    gemm_core<0, 1>(W, X, Y, s);
}

__global__ __launch_bounds__(256)
void gemm_out(const float* __restrict__ W, const float* __restrict__ X,
              float* __restrict__ Y)
{
    gemm_core<1, 0>(W, X, Y, 1.f);
}

// ---------------------------------------------------------------------------
// Attention: one warp per pixel, lane = 4-channel group (float4).
// Shared fractional weights => 25 taps collapse onto a 6x6 corner grid.
// Rolling horizontal-lerp rows; vertical lerp per tap.
// ---------------------------------------------------------------------------
__global__ __launch_bounds__(128)
void attn_kernel(const float* __restrict__ qp, const float* __restrict__ kp,
                 const float* __restrict__ vp, const float* __restrict__ flow,
                 float* __restrict__ attn_out, float* __restrict__ opre)
{
    const int warp = threadIdx.x >> 5;
    const int lane = threadIdx.x & 31;
    const int pix  = blockIdx.x * 4 + warp;
    const int n    = pix >> 12;
    const int yx   = pix & 4095;
    const int y    = yx >> 6;
    const int x    = yx & 63;
    const int head = lane >> 3;

    __shared__ float s_part[4][32][27];       // [warp][lane][kk], pad 27
    __shared__ float s_attn[4][NHEAD][K2];

    // ---- tap geometry (all registers, no smem) ----
    const float fx = flow[(size_t)(n * 2 + 0) * HW + yx];
    const float fy = flow[(size_t)(n * 2 + 1) * HW + yx];
    // reference's normalize->denormalize round trip on the base position
    float vxn = 2.0f * ((float)x + fx) / 63.0f - 1.0f;
    float vyn = 2.0f * ((float)y + fy) / 63.0f - 1.0f;
    float xs = (vxn + 1.0f) * 0.5f * 63.0f;
    float ys = (vyn + 1.0f) * 0.5f * 63.0f;
    float bxf = floorf(xs), byf = floorf(ys);
    const float wx = xs - bxf;
    const float wy = ys - byf;
    const int ibx = (int)bxf - 2;             // corner-grid origin
    const int iby = (int)byf - 2;

    unsigned mx = 0, my = 0;
    #pragma unroll
    for (int i = 0; i < 6; i++) {
        if ((unsigned)(ibx + i) <= 63u) mx |= 1u << i;
        if ((unsigned)(iby + i) <= 63u) my |= 1u << i;
    }

    const float4 q4 = *(const float4*)&qp[(size_t)pix * CC + lane * 4];
    const long long rowstride = (long long)WW * CC;
    const long long base0 = ((long long)(n << 12) + (long long)iby * WW + ibx) * CC
                          + lane * 4;

    // ================= K phase: logits =================
    {
        float4 Ha[5], Hb[5];
        #pragma unroll
        for (int jc = 0; jc < 6; jc++) {
            const float* rowp = kp + base0 + jc * rowstride;
            const bool rowok = (my >> jc) & 1;
            float4 c[6];
            #pragma unroll
            for (int i = 0; i < 6; i++) {
                c[i] = make_float4(0.f, 0.f, 0.f, 0.f);
                if (rowok && ((mx >> i) & 1))
                    c[i] = *(const float4*)(rowp + i * CC);
            }
            float4* Hc = (jc & 1) ? Hb : Ha;
            float4* Hp = (jc & 1) ? Ha : Hb;
            #pragma unroll
            for (int i = 0; i < 5; i++) {
                Hc[i].x = fmaf(wx, c[i+1].x - c[i].x, c[i].x);
                Hc[i].y = fmaf(wx, c[i+1].y - c[i].y, c[i].y);
                Hc[i].z = fmaf(wx, c[i+1].z - c[i].z, c[i].z);
                Hc[i].w = fmaf(wx, c[i+1].w - c[i].w, c[i].w);
            }
            if (jc > 0) {
                #pragma unroll
                for (int i = 0; i < 5; i++) {
                    float tx0 = fmaf(wy, Hc[i].x - Hp[i].x, Hp[i].x);
                    float ty0 = fmaf(wy, Hc[i].y - Hp[i].y, Hp[i].y);
                    float tz0 = fmaf(wy, Hc[i].z - Hp[i].z, Hp[i].z);
                    float tw0 = fmaf(wy, Hc[i].w - Hp[i].w, Hp[i].w);
                    float d = q4.x * tx0;
                    d = fmaf(q4.y, ty0, d);
                    d = fmaf(q4.z, tz0, d);
                    d = fmaf(q4.w, tw0, d);
                    s_part[warp][lane][(jc - 1) * 5 + i] = d;
                }
            }
        }
    }
    __syncwarp();

    // ---- reduce partials: lane kk sums 32 lanes into per-head logits ----
    const int kkl = (lane < K2) ? lane : 0;
    float hsum[4] = {0.f, 0.f, 0.f, 0.f};
    #pragma unroll
    for (int l = 0; l < 32; l++)
        hsum[l >> 3] += s_part[warp][l][kkl];

    // ---- softmax per head over kk (lanes 0..24) ----
    float aout[4];
    #pragma unroll
    for (int h = 0; h < 4; h++) {
        float lg = (lane < K2) ? hsum[h] : -INFINITY;
        float m = lg;
        #pragma unroll
        for (int off = 16; off; off >>= 1)
            m = fmaxf(m, __shfl_xor_sync(0xffffffffu, m, off));
        float e = (lane < K2) ? __expf(lg - m) : 0.f;
        float s = e;
        #pragma unroll
        for (int off = 16; off; off >>= 1)
            s += __shfl_xor_sync(0xffffffffu, s, off);
        aout[h] = e / s;
    }
    if (lane < K2) {
        #pragma unroll
        for (int h = 0; h < 4; h++) {
            s_attn[warp][h][lane] = aout[h];
            attn_out[(size_t)((n * NHEAD + h) * K2 + lane) * HW + yx] = aout[h];
        }
    }
    __syncwarp();

    // ================= V phase: weighted sum =================
    float4 out4 = make_float4(0.f, 0.f, 0.f, 0.f);
    {
        float4 Ha[5], Hb[5];
        #pragma unroll
        for (int jc = 0; jc < 6; jc++) {
            const float* rowp = vp + base0 + jc * rowstride;
            const bool rowok = (my >> jc) & 1;
            float4 c[6];
            #pragma unroll
            for (int i = 0; i < 6; i++) {
                c[i] = make_float4(0.f, 0.f, 0.f, 0.f);
                if (rowok && ((mx >> i) & 1))
                    c[i] = *(const float4*)(rowp + i * CC);
            }
            float4* Hc = (jc & 1) ? Hb : Ha;
            float4* Hp = (jc & 1) ? Ha : Hb;
            #pragma unroll
            for (int i = 0; i < 5; i++) {
                Hc[i].x = fmaf(wx, c[i+1].x - c[i].x, c[i].x);
                Hc[i].y = fmaf(wx, c[i+1].y - c[i].y, c[i].y);
                Hc[i].z = fmaf(wx, c[i+1].z - c[i].z, c[i].z);
                Hc[i].w = fmaf(wx, c[i+1].w - c[i].w, c[i].w);
            }
            if (jc > 0) {
                #pragma unroll
                for (int i = 0; i < 5; i++) {
                    float aw = s_attn[warp][head][(jc - 1) * 5 + i];
                    float tx0 = fmaf(wy, Hc[i].x - Hp[i].x, Hp[i].x);
                    float ty0 = fmaf(wy, Hc[i].y - Hp[i].y, Hp[i].y);
                    float tz0 = fmaf(wy, Hc[i].z - Hp[i].z, Hp[i].z);
                    float tw0 = fmaf(wy, Hc[i].w - Hp[i].w, Hp[i].w);
                    out4.x = fmaf(aw, tx0, out4.x);
                    out4.y = fmaf(aw, ty0, out4.y);
                    out4.z = fmaf(aw, tz0, out4.z);
                    out4.w = fmaf(aw, tw0, out4.w);
                }
            }
        }
    }
    *(float4*)&opre[(size_t)pix * CC + lane * 4] = out4;
}

// ---------------------------------------------------------------------------
extern "C" void kernel_launch(void* const* d_in, const int* in_sizes, int n_in,
                              void* d_out, int out_size)
{
    const float* q    = (const float*)d_in[0];
    const float* k    = (const float*)d_in[1];
    const float* v    = (const float*)d_in[2];
    const float* flow = (const float*)d_in[3];
    const float* Wq   = (const float*)d_in[4];
    const float* Wk   = (const float*)d_in[5];
    const float* Wv   = (const float*)d_in[6];
    const float* Wfc  = (const float*)d_in[7];

    float* out  = (float*)d_out;
    float* attn = out + (size_t)NB * CC * HW;

    float *qp, *kp, *vp, *opre;
    cudaGetSymbolAddress((void**)&qp,   g_qp);
    cudaGetSymbolAddress((void**)&kp,   g_kp);
    cudaGetSymbolAddress((void**)&vp,   g_vp);
    cudaGetSymbolAddress((void**)&opre, g_opre);

    const float qscale = 0.17677669529663687f;  // 1/sqrt(32)

    dim3 gqkv(HW / 128, NB, 3);                 // (32, 4, 3)
    gemm_qkv<<<gqkv, 256>>>(Wq, Wk, Wv, q, k, v, qp, kp, vp, qscale);

    attn_kernel<<<NPIX / 4, 128>>>(qp, kp, vp, flow, attn, opre);

    dim3 gg(HW / 128, NB);
    gemm_out<<<gg, 256>>>(Wfc, opre, out);
}

// round 3
// speedup vs baseline: 2.1081x; 1.0876x over previous
#include <cuda_runtime.h>
#include <math.h>
#include <stdint.h>

// ---------------------------------------------------------------------------
// n=4, C=128, H=W=64, K_SIZE=5 (K2=25), N_HEAD=4, d=32
// Inputs: q, k, v, flow, Wq, Wk, Wv, Wfc
// Output: concat( out[4,128,64,64], attn[4,4,25,64,64] )
// ---------------------------------------------------------------------------

#define NB      4
#define CC      128
#define WW      64
#define HW      4096
#define NPIX    (NB*HW)
#define PLANE   (CC*HW)
#define K2      25
#define NHEAD   4

#define PADX 33     // Xs row stride (pixel-major, 32 k + 1 pad)
#define PADW 36     // Ws row stride (o-major, 32 k + 4 pad) -> 4n+k hits banks 0..31
#define SMEM_U32 (2*128*PADX + 2*128*PADW)   // 17664 u32 = 70656 B

__device__ float g_qp[NB*HW*CC];    // NHWC, pre-scaled by 1/sqrt(d)
__device__ float g_kp[NB*HW*CC];    // NHWC
__device__ float g_vp[NB*HW*CC];    // NHWC
__device__ float g_opre[NB*HW*CC];  // NHWC

// ---------------------------------------------------------------------------
// tf32 helpers
// ---------------------------------------------------------------------------
__device__ __forceinline__ uint32_t cvt_tf32(float x) {
    uint32_t r;
    asm("cvt.rna.tf32.f32 %0, %1;" : "=r"(r) : "f"(x));
    return r;
}
__device__ __forceinline__ void split_tf32(float x, uint32_t& h, uint32_t& l) {
    h = cvt_tf32(x);
    l = cvt_tf32(x - __uint_as_float(h));
}
__device__ __forceinline__ void mma_tf32(float* c, const uint32_t* a,
                                         uint32_t b0, uint32_t b1) {
    asm volatile(
        "mma.sync.aligned.m16n8k8.row.col.f32.tf32.tf32.f32 "
        "{%0,%1,%2,%3}, {%4,%5,%6,%7}, {%8,%9}, {%0,%1,%2,%3};\n"
        : "+f"(c[0]), "+f"(c[1]), "+f"(c[2]), "+f"(c[3])
        : "r"(a[0]), "r"(a[1]), "r"(a[2]), "r"(a[3]), "r"(b0), "r"(b1));
}

// ---------------------------------------------------------------------------
// Tensor-core GEMM: C[p][o] = sum_k X[p][k] * W[o][k], 3-term tf32 split.
// BM=128 pixels, BN=128 outputs, BK=32. 8 warps: 4 (m) x 2 (n), warp 32x64.
// XMODE 0: X global is [k][p] (NCHW), XMODE 1: X is [p][k] (NHWC)
// YMODE 0: Y global is [o][p] (NCHW), YMODE 1: Y is [p][o] (NHWC)
// ---------------------------------------------------------------------------
template<int XMODE, int YMODE>
__device__ __forceinline__
void mma_gemm_core(const float* __restrict__ W, const float* __restrict__ X,
                   float* __restrict__ Y, float scale)
{
    extern __shared__ uint32_t sm[];
    uint32_t* XsH = sm;
    uint32_t* XsL = XsH + 128 * PADX;
    uint32_t* WsH = XsL + 128 * PADX;
    uint32_t* WsL = WsH + 128 * PADW;

    const int tid   = threadIdx.x;
    const int warp  = tid >> 5;
    const int lane  = tid & 31;
    const int qid   = lane >> 2;        // 0..7
    const int qlan  = lane & 3;         // 0..3
    const int pm    = (warp & 3) * 32;  // warp m-offset
    const int on    = (warp >> 2) * 64; // warp n-offset
    const int n     = blockIdx.y;
    const int pix0  = blockIdx.x * 128;

    const float* Xn = X + (size_t)n * PLANE;
    float*       Yn = Y + (size_t)n * PLANE;

    float acc[2][8][4];
    #pragma unroll
    for (int am = 0; am < 2; am++)
        #pragma unroll
        for (int bn = 0; bn < 8; bn++)
            #pragma unroll
            for (int j = 0; j < 4; j++) acc[am][bn][j] = 0.f;

    for (int k0 = 0; k0 < 128; k0 += 32) {
        __syncthreads();   // protect smem from previous iteration's readers

        // ---- load W tile (128 o x 32 k), split hi/lo ----
        #pragma unroll
        for (int it = 0; it < 16; it++) {
            int i = tid + it * 256;
            int o = i >> 5, kk = i & 31;
            float v = W[o * 128 + k0 + kk];
            uint32_t h, l; split_tf32(v, h, l);
            WsH[o * PADW + kk] = h;
            WsL[o * PADW + kk] = l;
        }
        // ---- load X tile (128 p x 32 k), split hi/lo ----
        if (XMODE == 0) {
            #pragma unroll
            for (int it = 0; it < 16; it++) {
                int i = tid + it * 256;
                int kk = i >> 7, p = i & 127;
                float v = Xn[(size_t)(k0 + kk) * HW + pix0 + p];
                uint32_t h, l; split_tf32(v, h, l);
                XsH[p * PADX + kk] = h;
                XsL[p * PADX + kk] = l;
            }
        } else {
            #pragma unroll
            for (int it = 0; it < 16; it++) {
                int i = tid + it * 256;
                int p = i >> 5, kk = i & 31;
                float v = Xn[(size_t)(pix0 + p) * CC + k0 + kk];
                uint32_t h, l; split_tf32(v, h, l);
                XsH[p * PADX + kk] = h;
                XsL[p * PADX + kk] = l;
            }
        }
        __syncthreads();

        // ---- compute: 4 k-steps of 8 ----
        #pragma unroll
        for (int ks = 0; ks < 4; ks++) {
            const int kb = ks * 8 + qlan;

            uint32_t aH[2][4], aL[2][4];
            #pragma unroll
            for (int am = 0; am < 2; am++) {
                int r = pm + am * 16 + qid;
                int b0 = r * PADX + kb;
                aH[am][0] = XsH[b0];
                aH[am][1] = XsH[b0 + 8 * PADX];
                aH[am][2] = XsH[b0 + 4];
                aH[am][3] = XsH[b0 + 8 * PADX + 4];
                aL[am][0] = XsL[b0];
                aL[am][1] = XsL[b0 + 8 * PADX];
                aL[am][2] = XsL[b0 + 4];
                aL[am][3] = XsL[b0 + 8 * PADX + 4];
            }
            #pragma unroll
            for (int bn = 0; bn < 8; bn++) {
                int nn = on + bn * 8 + qid;
                int bb = nn * PADW + kb;
                uint32_t bH0 = WsH[bb], bH1 = WsH[bb + 4];
                uint32_t bL0 = WsL[bb], bL1 = WsL[bb + 4];
                #pragma unroll
                for (int am = 0; am < 2; am++) {
                    mma_tf32(acc[am][bn], aH[am], bH0, bH1);
                    mma_tf32(acc[am][bn], aH[am], bL0, bL1);
                    mma_tf32(acc[am][bn], aL[am], bH0, bH1);
                }
            }
        }
    }

    // ---- epilogue ----
    if (YMODE == 1) {
        // Y[p][o] (NHWC): c0,c1 adjacent in o -> float2 stores
        #pragma unroll
        for (int am = 0; am < 2; am++) {
            int p0 = pix0 + pm + am * 16 + qid;
            #pragma unroll
            for (int bn = 0; bn < 8; bn++) {
                int o = on + bn * 8 + 2 * qlan;
                float2 v0 = make_float2(acc[am][bn][0] * scale,
                                        acc[am][bn][1] * scale);
                float2 v1 = make_float2(acc[am][bn][2] * scale,
                                        acc[am][bn][3] * scale);
                *(float2*)&Yn[(size_t)p0 * CC + o]       = v0;
                *(float2*)&Yn[(size_t)(p0 + 8) * CC + o] = v1;
            }
        }
    } else {
        // Y[o][p] (NCHW): scalar stores
        #pragma unroll
        for (int am = 0; am < 2; am++) {
            int p0 = pix0 + pm + am * 16 + qid;
            #pragma unroll
            for (int bn = 0; bn < 8; bn++) {
                int o = on + bn * 8 + 2 * qlan;
                Yn[(size_t)o * HW + p0]           = acc[am][bn][0] * scale;
                Yn[(size_t)(o + 1) * HW + p0]     = acc[am][bn][1] * scale;
                Yn[(size_t)o * HW + p0 + 8]       = acc[am][bn][2] * scale;
                Yn[(size_t)(o + 1) * HW + p0 + 8] = acc[am][bn][3] * scale;
            }
        }
    }
}

// Fused q/k/v projections: blockIdx.z selects which GEMM
__global__ __launch_bounds__(256)
void gemm_qkv(const float* __restrict__ Wq, const float* __restrict__ Wk,
              const float* __restrict__ Wv,
              const float* __restrict__ q, const float* __restrict__ k,
              const float* __restrict__ v,
              float* __restrict__ qp, float* __restrict__ kp,
              float* __restrict__ vp, float qscale)
{
    const float* W; const float* X; float* Y; float s;
    if (blockIdx.z == 0)      { W = Wq; X = q; Y = qp; s = qscale; }
    else if (blockIdx.z == 1) { W = Wk; X = k; Y = kp; s = 1.f; }
    else                      { W = Wv; X = v; Y = vp; s = 1.f; }
    mma_gemm_core<0, 1>(W, X, Y, s);
}

__global__ __launch_bounds__(256)
void gemm_out(const float* __restrict__ W, const float* __restrict__ X,
              float* __restrict__ Y)
{
    mma_gemm_core<1, 0>(W, X, Y, 1.f);
}

// ---------------------------------------------------------------------------
// Attention: one warp per pixel, lane = 4-channel group (float4).
// 25 taps share fractional weights => collapse onto a 6x6 corner grid.
// ---------------------------------------------------------------------------
__global__ __launch_bounds__(128)
void attn_kernel(const float* __restrict__ qp, const float* __restrict__ kp,
                 const float* __restrict__ vp, const float* __restrict__ flow,
                 float* __restrict__ attn_out, float* __restrict__ opre)
{
    const int warp = threadIdx.x >> 5;
    const int lane = threadIdx.x & 31;
    const int pix  = blockIdx.x * 4 + warp;
    const int n    = pix >> 12;
    const int yx   = pix & 4095;
    const int y    = yx >> 6;
    const int x    = yx & 63;
    const int head = lane >> 3;

    __shared__ float s_part[4][32][27];
    __shared__ float s_attn[4][NHEAD][K2];

    const float fx = flow[(size_t)(n * 2 + 0) * HW + yx];
    const float fy = flow[(size_t)(n * 2 + 1) * HW + yx];
    float vxn = 2.0f * ((float)x + fx) / 63.0f - 1.0f;
    float vyn = 2.0f * ((float)y + fy) / 63.0f - 1.0f;
    float xs = (vxn + 1.0f) * 0.5f * 63.0f;
    float ys = (vyn + 1.0f) * 0.5f * 63.0f;
    float bxf = floorf(xs), byf = floorf(ys);
    const float wx = xs - bxf;
    const float wy = ys - byf;
    const int ibx = (int)bxf - 2;
    const int iby = (int)byf - 2;

    unsigned mx = 0, my = 0;
    #pragma unroll
    for (int i = 0; i < 6; i++) {
        if ((unsigned)(ibx + i) <= 63u) mx |= 1u << i;
        if ((unsigned)(iby + i) <= 63u) my |= 1u << i;
    }

    const float4 q4 = *(const float4*)&qp[(size_t)pix * CC + lane * 4];
    const long long rowstride = (long long)WW * CC;
    const long long base0 = ((long long)(n << 12) + (long long)iby * WW + ibx) * CC
                          + lane * 4;

    // ================= K phase: logits =================
    {
        float4 Ha[5], Hb[5];
        #pragma unroll
        for (int jc = 0; jc < 6; jc++) {
            const float* rowp = kp + base0 + jc * rowstride;
            const bool rowok = (my >> jc) & 1;
            float4 c[6];
            #pragma unroll
            for (int i = 0; i < 6; i++) {
                c[i] = make_float4(0.f, 0.f, 0.f, 0.f);
                if (rowok && ((mx >> i) & 1))
                    c[i] = *(const float4*)(rowp + i * CC);
            }
            float4* Hc = (jc & 1) ? Hb : Ha;
            float4* Hp = (jc & 1) ? Ha : Hb;
            #pragma unroll
            for (int i = 0; i < 5; i++) {
                Hc[i].x = fmaf(wx, c[i+1].x - c[i].x, c[i].x);
                Hc[i].y = fmaf(wx, c[i+1].y - c[i].y, c[i].y);
                Hc[i].z = fmaf(wx, c[i+1].z - c[i].z, c[i].z);
                Hc[i].w = fmaf(wx, c[i+1].w - c[i].w, c[i].w);
            }
            if (jc > 0) {
                #pragma unroll
                for (int i = 0; i < 5; i++) {
                    float tx0 = fmaf(wy, Hc[i].x - Hp[i].x, Hp[i].x);
                    float ty0 = fmaf(wy, Hc[i].y - Hp[i].y, Hp[i].y);
                    float tz0 = fmaf(wy, Hc[i].z - Hp[i].z, Hp[i].z);
                    float tw0 = fmaf(wy, Hc[i].w - Hp[i].w, Hp[i].w);
                    float d = q4.x * tx0;
                    d = fmaf(q4.y, ty0, d);
                    d = fmaf(q4.z, tz0, d);
                    d = fmaf(q4.w, tw0, d);
                    s_part[warp][lane][(jc - 1) * 5 + i] = d;
                }
            }
        }
    }
    __syncwarp();

    const int kkl = (lane < K2) ? lane : 0;
    float hsum[4] = {0.f, 0.f, 0.f, 0.f};
    #pragma unroll
    for (int l = 0; l < 32; l++)
        hsum[l >> 3] += s_part[warp][l][kkl];

    float aout[4];
    #pragma unroll
    for (int h = 0; h < 4; h++) {
        float lg = (lane < K2) ? hsum[h] : -INFINITY;
        float m = lg;
        #pragma unroll
        for (int off = 16; off; off >>= 1)
            m = fmaxf(m, __shfl_xor_sync(0xffffffffu, m, off));
        float e = (lane < K2) ? __expf(lg - m) : 0.f;
        float s = e;
        #pragma unroll
        for (int off = 16; off; off >>= 1)
            s += __shfl_xor_sync(0xffffffffu, s, off);
        aout[h] = e / s;
    }
    if (lane < K2) {
        #pragma unroll
        for (int h = 0; h < 4; h++) {
            s_attn[warp][h][lane] = aout[h];
            attn_out[(size_t)((n * NHEAD + h) * K2 + lane) * HW + yx] = aout[h];
        }
    }
    __syncwarp();

    // ================= V phase =================
    float4 out4 = make_float4(0.f, 0.f, 0.f, 0.f);
    {
        float4 Ha[5], Hb[5];
        #pragma unroll
        for (int jc = 0; jc < 6; jc++) {
            const float* rowp = vp + base0 + jc * rowstride;
            const bool rowok = (my >> jc) & 1;
            float4 c[6];
            #pragma unroll
            for (int i = 0; i < 6; i++) {
                c[i] = make_float4(0.f, 0.f, 0.f, 0.f);
                if (rowok && ((mx >> i) & 1))
                    c[i] = *(const float4*)(rowp + i * CC);
            }
            float4* Hc = (jc & 1) ? Hb : Ha;
            float4* Hp = (jc & 1) ? Ha : Hb;
            #pragma unroll
            for (int i = 0; i < 5; i++) {
                Hc[i].x = fmaf(wx, c[i+1].x - c[i].x, c[i].x);
                Hc[i].y = fmaf(wx, c[i+1].y - c[i].y, c[i].y);
                Hc[i].z = fmaf(wx, c[i+1].z - c[i].z, c[i].z);
                Hc[i].w = fmaf(wx, c[i+1].w - c[i].w, c[i].w);
            }
            if (jc > 0) {
                #pragma unroll
                for (int i = 0; i < 5; i++) {
                    float aw = s_attn[warp][head][(jc - 1) * 5 + i];
                    float tx0 = fmaf(wy, Hc[i].x - Hp[i].x, Hp[i].x);
                    float ty0 = fmaf(wy, Hc[i].y - Hp[i].y, Hp[i].y);
                    float tz0 = fmaf(wy, Hc[i].z - Hp[i].z, Hp[i].z);
                    float tw0 = fmaf(wy, Hc[i].w - Hp[i].w, Hp[i].w);
                    out4.x = fmaf(aw, tx0, out4.x);
                    out4.y = fmaf(aw, ty0, out4.y);
                    out4.z = fmaf(aw, tz0, out4.z);
                    out4.w = fmaf(aw, tw0, out4.w);
                }
            }
        }
    }
    *(float4*)&opre[(size_t)pix * CC + lane * 4] = out4;
}

// ---------------------------------------------------------------------------
extern "C" void kernel_launch(void* const* d_in, const int* in_sizes, int n_in,
                              void* d_out, int out_size)
{
    const float* q    = (const float*)d_in[0];
    const float* k    = (const float*)d_in[1];
    const float* v    = (const float*)d_in[2];
    const float* flow = (const float*)d_in[3];
    const float* Wq   = (const float*)d_in[4];
    const float* Wk   = (const float*)d_in[5];
    const float* Wv   = (const float*)d_in[6];
    const float* Wfc  = (const float*)d_in[7];

    float* out  = (float*)d_out;
    float* attn = out + (size_t)NB * CC * HW;

    float *qp, *kp, *vp, *opre;
    cudaGetSymbolAddress((void**)&qp,   g_qp);
    cudaGetSymbolAddress((void**)&kp,   g_kp);
    cudaGetSymbolAddress((void**)&vp,   g_vp);
    cudaGetSymbolAddress((void**)&opre, g_opre);

    const size_t smem_bytes = SMEM_U32 * sizeof(uint32_t);   // 70656
    cudaFuncSetAttribute(gemm_qkv, cudaFuncAttributeMaxDynamicSharedMemorySize,
                         (int)smem_bytes);
    cudaFuncSetAttribute(gemm_out, cudaFuncAttributeMaxDynamicSharedMemorySize,
                         (int)smem_bytes);

    const float qscale = 0.17677669529663687f;  // 1/sqrt(32)

    dim3 gqkv(HW / 128, NB, 3);
    gemm_qkv<<<gqkv, 256, smem_bytes>>>(Wq, Wk, Wv, q, k, v, qp, kp, vp, qscale);

    attn_kernel<<<NPIX / 4, 128>>>(qp, kp, vp, flow, attn, opre);

    dim3 gg(HW / 128, NB);
    gemm_out<<<gg, 256, smem_bytes>>>(Wfc, opre, out);
}

// round 4
// speedup vs baseline: 2.4479x; 1.1612x over previous
#include <cuda_runtime.h>
#include <math.h>
#include <stdint.h>

// ---------------------------------------------------------------------------
// n=4, C=128, H=W=64, K_SIZE=5 (K2=25), N_HEAD=4, d=32
// Inputs: q, k, v, flow, Wq, Wk, Wv, Wfc
// Output: concat( out[4,128,64,64], attn[4,4,25,64,64] )
// ---------------------------------------------------------------------------

#define NB      4
#define CC      128
#define WW      64
#define HW      4096
#define NPIX    (NB*HW)
#define PLANE   (CC*HW)
#define K2      25
#define NHEAD   4

// smem layout (u32 units):
//   Xs  f32 raw:  XMODE0 k-major [32][136]=4352, XMODE1 p-major [128][36]=4608
//   WsH tf32 hi:  [128][36] = 4608
//   WsL tf32 lo:  [128][36] = 4608
#define XS_SZ   4608
#define WS_OFF  4608
#define SMEM_U32 (4608*3)               // 13824 u32 = 55296 B
#define PXK     136                     // X k-major row stride (mod 32 = 8)
#define PW      36                      // W / X p-major row stride (mod 32 = 4)

__device__ float g_qp[NB*HW*CC];    // NHWC, pre-scaled by 1/sqrt(d)
__device__ float g_kp[NB*HW*CC];    // NHWC
__device__ float g_vp[NB*HW*CC];    // NHWC
__device__ float g_opre[NB*HW*CC];  // NHWC

// ---------------------------------------------------------------------------
// helpers
// ---------------------------------------------------------------------------
__device__ __forceinline__ uint32_t cvt_tf32(float x) {
    uint32_t r;
    asm("cvt.rna.tf32.f32 %0, %1;" : "=r"(r) : "f"(x));
    return r;
}
__device__ __forceinline__ void split_tf32(float x, uint32_t& h, uint32_t& l) {
    h = cvt_tf32(x);
    l = cvt_tf32(x - __uint_as_float(h));
}
__device__ __forceinline__ void mma_tf32(float* c, const uint32_t* a,
                                         uint32_t b0, uint32_t b1) {
    asm volatile(
        "mma.sync.aligned.m16n8k8.row.col.f32.tf32.tf32.f32 "
        "{%0,%1,%2,%3}, {%4,%5,%6,%7}, {%8,%9}, {%0,%1,%2,%3};\n"
        : "+f"(c[0]), "+f"(c[1]), "+f"(c[2]), "+f"(c[3])
        : "r"(a[0]), "r"(a[1]), "r"(a[2]), "r"(a[3]), "r"(b0), "r"(b1));
}
__device__ __forceinline__ void cp_async16(uint32_t dst_smem, const void* src) {
    asm volatile("cp.async.cg.shared.global [%0], [%1], 16;\n"
                 :: "r"(dst_smem), "l"(src));
}

// ---------------------------------------------------------------------------
// Tensor-core GEMM: C[p][o] = sum_k X[p][k] * W[o][k], 3-term tf32 split.
// BM=128 pix, BN=128 out, BK=32. 8 warps: 4(m) x 2(n), warp tile 32x64.
// X raw f32 in smem (register-side split); W pre-split hi/lo in smem.
// XMODE 0: X global [k][p] (NCHW) -> smem k-major [kk][p] stride 136
// XMODE 1: X global [p][k] (NHWC) -> smem p-major [p][kk] stride 36
// YMODE 0: Y [o][p] (NCHW), YMODE 1: Y [p][o] (NHWC)
// ---------------------------------------------------------------------------
template<int XMODE, int YMODE>
__device__ __forceinline__
void mma_gemm_core(const float* __restrict__ W, const float* __restrict__ X,
                   float* __restrict__ Y, float scale)
{
    extern __shared__ uint32_t sm[];
    float*    Xs  = (float*)sm;
    uint32_t* WsH = sm + WS_OFF;
    uint32_t* WsL = sm + WS_OFF + 4608;

    const int tid   = threadIdx.x;
    const int warp  = tid >> 5;
    const int lane  = tid & 31;
    const int qid   = lane >> 2;        // 0..7
    const int qlan  = lane & 3;         // 0..3
    const int pm    = (warp & 3) * 32;  // warp m-offset
    const int on    = (warp >> 2) * 64; // warp n-offset
    const int n     = blockIdx.y;
    const int pix0  = blockIdx.x * 128;

    const float* Xn = X + (size_t)n * PLANE;
    float*       Yn = Y + (size_t)n * PLANE;

    const uint32_t xs_base = (uint32_t)__cvta_generic_to_shared(Xs);

    float acc[2][8][4];
    #pragma unroll
    for (int am = 0; am < 2; am++)
        #pragma unroll
        for (int bn = 0; bn < 8; bn++)
            #pragma unroll
            for (int j = 0; j < 4; j++) acc[am][bn][j] = 0.f;

    for (int k0 = 0; k0 < 128; k0 += 32) {
        __syncthreads();   // previous iteration's readers done

        // ---- X tile via cp.async (raw f32) ----
        if (XMODE == 0) {
            // rows = kk (32), each row 128 contiguous pixels = 32 x 16B
            #pragma unroll
            for (int it = 0; it < 4; it++) {
                int idx = tid + it * 256;       // 0..1023
                int kk = idx >> 5, c = idx & 31;
                const float* src = Xn + (size_t)(k0 + kk) * HW + pix0 + c * 4;
                cp_async16(xs_base + (uint32_t)(kk * PXK + c * 4) * 4, src);
            }
        } else {
            // rows = p (128), each row 32 contiguous k = 8 x 16B
            #pragma unroll
            for (int it = 0; it < 4; it++) {
                int idx = tid + it * 256;
                int p = idx >> 3, c = idx & 7;
                const float* src = Xn + (size_t)(pix0 + p) * CC + k0 + c * 4;
                cp_async16(xs_base + (uint32_t)(p * PW + c * 4) * 4, src);
            }
        }
        asm volatile("cp.async.commit_group;\n");

        // ---- W tile: load + split hi/lo ----
        #pragma unroll
        for (int it = 0; it < 16; it++) {
            int idx = tid + it * 256;
            int o = idx >> 5, kk = idx & 31;
            float v = W[o * 128 + k0 + kk];
            uint32_t h, l; split_tf32(v, h, l);
            WsH[o * PW + kk] = h;
            WsL[o * PW + kk] = l;
        }
        asm volatile("cp.async.wait_group 0;\n");
        __syncthreads();

        // ---- compute: 4 k-steps of 8 ----
        #pragma unroll
        for (int ks = 0; ks < 4; ks++) {
            const int kb = ks * 8 + qlan;

            uint32_t aH[2][4], aL[2][4];
            #pragma unroll
            for (int am = 0; am < 2; am++) {
                int r = pm + am * 16 + qid;
                float f0, f1, f2, f3;
                if (XMODE == 0) {
                    f0 = Xs[kb * PXK + r];
                    f1 = Xs[kb * PXK + r + 8];
                    f2 = Xs[(kb + 4) * PXK + r];
                    f3 = Xs[(kb + 4) * PXK + r + 8];
                } else {
                    f0 = Xs[r * PW + kb];
                    f1 = Xs[(r + 8) * PW + kb];
                    f2 = Xs[r * PW + kb + 4];
                    f3 = Xs[(r + 8) * PW + kb + 4];
                }
                split_tf32(f0, aH[am][0], aL[am][0]);
                split_tf32(f1, aH[am][1], aL[am][1]);
                split_tf32(f2, aH[am][2], aL[am][2]);
                split_tf32(f3, aH[am][3], aL[am][3]);
            }
            #pragma unroll
            for (int bn = 0; bn < 8; bn++) {
                int bb = (on + bn * 8 + qid) * PW + kb;
                uint32_t bH0 = WsH[bb], bH1 = WsH[bb + 4];
                uint32_t bL0 = WsL[bb], bL1 = WsL[bb + 4];
                #pragma unroll
                for (int am = 0; am < 2; am++) {
                    mma_tf32(acc[am][bn], aH[am], bH0, bH1);
                    mma_tf32(acc[am][bn], aH[am], bL0, bL1);
                    mma_tf32(acc[am][bn], aL[am], bH0, bH1);
                }
            }
        }
    }

    // ---- epilogue ----
    if (YMODE == 1) {
        #pragma unroll
        for (int am = 0; am < 2; am++) {
            int p0 = pix0 + pm + am * 16 + qid;
            #pragma unroll
            for (int bn = 0; bn < 8; bn++) {
                int o = on + bn * 8 + 2 * qlan;
                float2 v0 = make_float2(acc[am][bn][0] * scale,
                                        acc[am][bn][1] * scale);
                float2 v1 = make_float2(acc[am][bn][2] * scale,
                                        acc[am][bn][3] * scale);
                *(float2*)&Yn[(size_t)p0 * CC + o]       = v0;
                *(float2*)&Yn[(size_t)(p0 + 8) * CC + o] = v1;
            }
        }
    } else {
        #pragma unroll
        for (int am = 0; am < 2; am++) {
            int p0 = pix0 + pm + am * 16 + qid;
            #pragma unroll
            for (int bn = 0; bn < 8; bn++) {
                int o = on + bn * 8 + 2 * qlan;
                Yn[(size_t)o * HW + p0]           = acc[am][bn][0] * scale;
                Yn[(size_t)(o + 1) * HW + p0]     = acc[am][bn][1] * scale;
                Yn[(size_t)o * HW + p0 + 8]       = acc[am][bn][2] * scale;
                Yn[(size_t)(o + 1) * HW + p0 + 8] = acc[am][bn][3] * scale;
            }
        }
    }
}

// Fused q/k/v projections: blockIdx.z selects which GEMM
__global__ __launch_bounds__(256, 2)
void gemm_qkv(const float* __restrict__ Wq, const float* __restrict__ Wk,
              const float* __restrict__ Wv,
              const float* __restrict__ q, const float* __restrict__ k,
              const float* __restrict__ v,
              float* __restrict__ qp, float* __restrict__ kp,
              float* __restrict__ vp, float qscale)
{
    const float* W; const float* X; float* Y; float s;
    if (blockIdx.z == 0)      { W = Wq; X = q; Y = qp; s = qscale; }
    else if (blockIdx.z == 1) { W = Wk; X = k; Y = kp; s = 1.f; }
    else                      { W = Wv; X = v; Y = vp; s = 1.f; }
    mma_gemm_core<0, 1>(W, X, Y, s);
}

__global__ __launch_bounds__(256, 2)
void gemm_out(const float* __restrict__ W, const float* __restrict__ X,
              float* __restrict__ Y)
{
    mma_gemm_core<1, 0>(W, X, Y, 1.f);
}

// ---------------------------------------------------------------------------
// Attention: one warp per pixel, lane = 4-channel group (float4).
// 25 taps share fractional weights => collapse onto a 6x6 corner grid.
// ---------------------------------------------------------------------------
__global__ __launch_bounds__(128)
void attn_kernel(const float* __restrict__ qp, const float* __restrict__ kp,
                 const float* __restrict__ vp, const float* __restrict__ flow,
                 float* __restrict__ attn_out, float* __restrict__ opre)
{
    const int warp = threadIdx.x >> 5;
    const int lane = threadIdx.x & 31;
    const int pix  = blockIdx.x * 4 + warp;
    const int n    = pix >> 12;
    const int yx   = pix & 4095;
    const int y    = yx >> 6;
    const int x    = yx & 63;
    const int head = lane >> 3;

    __shared__ float s_part[4][32][27];
    __shared__ float s_attn[4][NHEAD][K2];

    const float fx = flow[(size_t)(n * 2 + 0) * HW + yx];
    const float fy = flow[(size_t)(n * 2 + 1) * HW + yx];
    float vxn = 2.0f * ((float)x + fx) / 63.0f - 1.0f;
    float vyn = 2.0f * ((float)y + fy) / 63.0f - 1.0f;
    float xs = (vxn + 1.0f) * 0.5f * 63.0f;
    float ys = (vyn + 1.0f) * 0.5f * 63.0f;
    float bxf = floorf(xs), byf = floorf(ys);
    const float wx = xs - bxf;
    const float wy = ys - byf;
    const int ibx = (int)bxf - 2;
    const int iby = (int)byf - 2;

    unsigned mx = 0, my = 0;
    #pragma unroll
    for (int i = 0; i < 6; i++) {
        if ((unsigned)(ibx + i) <= 63u) mx |= 1u << i;
        if ((unsigned)(iby + i) <= 63u) my |= 1u << i;
    }

    const float4 q4 = *(const float4*)&qp[(size_t)pix * CC + lane * 4];
    const long long rowstride = (long long)WW * CC;
    const long long base0 = ((long long)(n << 12) + (long long)iby * WW + ibx) * CC
                          + lane * 4;

    // ================= K phase: logits =================
    {
        float4 Ha[5], Hb[5];
        #pragma unroll
        for (int jc = 0; jc < 6; jc++) {
            const float* rowp = kp + base0 + jc * rowstride;
            const bool rowok = (my >> jc) & 1;
            float4 c[6];
            #pragma unroll
            for (int i = 0; i < 6; i++) {
                c[i] = make_float4(0.f, 0.f, 0.f, 0.f);
                if (rowok && ((mx >> i) & 1))
                    c[i] = *(const float4*)(rowp + i * CC);
            }
            float4* Hc = (jc & 1) ? Hb : Ha;
            float4* Hp = (jc & 1) ? Ha : Hb;
            #pragma unroll
            for (int i = 0; i < 5; i++) {
                Hc[i].x = fmaf(wx, c[i+1].x - c[i].x, c[i].x);
                Hc[i].y = fmaf(wx, c[i+1].y - c[i].y, c[i].y);
                Hc[i].z = fmaf(wx, c[i+1].z - c[i].z, c[i].z);
                Hc[i].w = fmaf(wx, c[i+1].w - c[i].w, c[i].w);
            }
            if (jc > 0) {
                #pragma unroll
                for (int i = 0; i < 5; i++) {
                    float tx0 = fmaf(wy, Hc[i].x - Hp[i].x, Hp[i].x);
                    float ty0 = fmaf(wy, Hc[i].y - Hp[i].y, Hp[i].y);
                    float tz0 = fmaf(wy, Hc[i].z - Hp[i].z, Hp[i].z);
                    float tw0 = fmaf(wy, Hc[i].w - Hp[i].w, Hp[i].w);
                    float d = q4.x * tx0;
                    d = fmaf(q4.y, ty0, d);
                    d = fmaf(q4.z, tz0, d);
                    d = fmaf(q4.w, tw0, d);
                    s_part[warp][lane][(jc - 1) * 5 + i] = d;
                }
            }
        }
    }
    __syncwarp();

    const int kkl = (lane < K2) ? lane : 0;
    float hsum[4] = {0.f, 0.f, 0.f, 0.f};
    #pragma unroll
    for (int l = 0; l < 32; l++)
        hsum[l >> 3] += s_part[warp][l][kkl];

    float aout[4];
    #pragma unroll
    for (int h = 0; h < 4; h++) {
        float lg = (lane < K2) ? hsum[h] : -INFINITY;
        float m = lg;
        #pragma unroll
        for (int off = 16; off; off >>= 1)
            m = fmaxf(m, __shfl_xor_sync(0xffffffffu, m, off));
        float e = (lane < K2) ? __expf(lg - m) : 0.f;
        float s = e;
        #pragma unroll
        for (int off = 16; off; off >>= 1)
            s += __shfl_xor_sync(0xffffffffu, s, off);
        aout[h] = e / s;
    }
    if (lane < K2) {
        #pragma unroll
        for (int h = 0; h < 4; h++) {
            s_attn[warp][h][lane] = aout[h];
            attn_out[(size_t)((n * NHEAD + h) * K2 + lane) * HW + yx] = aout[h];
        }
    }
    __syncwarp();

    // ================= V phase =================
    float4 out4 = make_float4(0.f, 0.f, 0.f, 0.f);
    {
        float4 Ha[5], Hb[5];
        #pragma unroll
        for (int jc = 0; jc < 6; jc++) {
            const float* rowp = vp + base0 + jc * rowstride;
            const bool rowok = (my >> jc) & 1;
            float4 c[6];
            #pragma unroll
            for (int i = 0; i < 6; i++) {
                c[i] = make_float4(0.f, 0.f, 0.f, 0.f);
                if (rowok && ((mx >> i) & 1))
                    c[i] = *(const float4*)(rowp + i * CC);
            }
            float4* Hc = (jc & 1) ? Hb : Ha;
            float4* Hp = (jc & 1) ? Ha : Hb;
            #pragma unroll
            for (int i = 0; i < 5; i++) {
                Hc[i].x = fmaf(wx, c[i+1].x - c[i].x, c[i].x);
                Hc[i].y = fmaf(wx, c[i+1].y - c[i].y, c[i].y);
                Hc[i].z = fmaf(wx, c[i+1].z - c[i].z, c[i].z);
                Hc[i].w = fmaf(wx, c[i+1].w - c[i].w, c[i].w);
            }
            if (jc > 0) {
                #pragma unroll
                for (int i = 0; i < 5; i++) {
                    float aw = s_attn[warp][head][(jc - 1) * 5 + i];
                    float tx0 = fmaf(wy, Hc[i].x - Hp[i].x, Hp[i].x);
                    float ty0 = fmaf(wy, Hc[i].y - Hp[i].y, Hp[i].y);
                    float tz0 = fmaf(wy, Hc[i].z - Hp[i].z, Hp[i].z);
                    float tw0 = fmaf(wy, Hc[i].w - Hp[i].w, Hp[i].w);
                    out4.x = fmaf(aw, tx0, out4.x);
                    out4.y = fmaf(aw, ty0, out4.y);
                    out4.z = fmaf(aw, tz0, out4.z);
                    out4.w = fmaf(aw, tw0, out4.w);
                }
            }
        }
    }
    *(float4*)&opre[(size_t)pix * CC + lane * 4] = out4;
}

// ---------------------------------------------------------------------------
extern "C" void kernel_launch(void* const* d_in, const int* in_sizes, int n_in,
                              void* d_out, int out_size)
{
    const float* q    = (const float*)d_in[0];
    const float* k    = (const float*)d_in[1];
    const float* v    = (const float*)d_in[2];
    const float* flow = (const float*)d_in[3];
    const float* Wq   = (const float*)d_in[4];
    const float* Wk   = (const float*)d_in[5];
    const float* Wv   = (const float*)d_in[6];
    const float* Wfc  = (const float*)d_in[7];

    float* out  = (float*)d_out;
    float* attn = out + (size_t)NB * CC * HW;

    float *qp, *kp, *vp, *opre;
    cudaGetSymbolAddress((void**)&qp,   g_qp);
    cudaGetSymbolAddress((void**)&kp,   g_kp);
    cudaGetSymbolAddress((void**)&vp,   g_vp);
    cudaGetSymbolAddress((void**)&opre, g_opre);

    const size_t smem_bytes = SMEM_U32 * sizeof(uint32_t);   // 55296
    cudaFuncSetAttribute(gemm_qkv, cudaFuncAttributeMaxDynamicSharedMemorySize,
                         (int)smem_bytes);
    cudaFuncSetAttribute(gemm_out, cudaFuncAttributeMaxDynamicSharedMemorySize,
                         (int)smem_bytes);

    const float qscale = 0.17677669529663687f;  // 1/sqrt(32)

    dim3 gqkv(HW / 128, NB, 3);
    gemm_qkv<<<gqkv, 256, smem_bytes>>>(Wq, Wk, Wv, q, k, v, qp, kp, vp, qscale);

    attn_kernel<<<NPIX / 4, 128>>>(qp, kp, vp, flow, attn, opre);

    dim3 gg(HW / 128, NB);
    gemm_out<<<gg, 256, smem_bytes>>>(Wfc, opre, out);
}

// round 5
// speedup vs baseline: 2.9012x; 1.1852x over previous
#include <cuda_runtime.h>
#include <cuda_bf16.h>
#include <math.h>
#include <stdint.h>

// ---------------------------------------------------------------------------
// n=4, C=128, H=W=64, K_SIZE=5 (K2=25), N_HEAD=4, d=32
// Inputs: q, k, v, flow, Wq, Wk, Wv, Wfc
// Output: concat( out[4,128,64,64], attn[4,4,25,64,64] )
// ---------------------------------------------------------------------------

#define NB      4
#define CC      128
#define WW      64
#define HW      4096
#define NPIX    (NB*HW)
#define PLANE   (CC*HW)
#define K2      25
#define NHEAD   4

// GEMM smem layout (u32 units)
#define PXK     132                 // X k-major row stride (mod 16 = 4; banks 8*qlan+qid)
#define PX1     40                  // X p-major row stride (LDS.64 conflict-free/phase)
#define PW2     20                  // W packed-bf16 row stride (banks 20*qid+qlan all distinct)
#define XS_CAP  5120                // max X tile: 128*40
#define SMEM_U32 (XS_CAP + 2*128*PW2)   // 5120 + 5120 = 10240 u32 = 40960 B

__device__ float g_qp[NB*HW*CC];    // NHWC, pre-scaled by 1/sqrt(d)
__device__ float g_kp[NB*HW*CC];    // NHWC
__device__ float g_vp[NB*HW*CC];    // NHWC
__device__ float g_opre[NB*HW*CC];  // NHWC

// ---------------------------------------------------------------------------
// bf16x3 helpers
// ---------------------------------------------------------------------------
__device__ __forceinline__ uint16_t bfb(float f) {
    __nv_bfloat16 h = __float2bfloat16_rn(f);
    return *reinterpret_cast<uint16_t*>(&h);
}
// split two f32 into packed bf16 hi pair + lo pair (lo16 = first/even k)
__device__ __forceinline__ void sp2(float f0, float f1, uint32_t& ph, uint32_t& pl) {
    uint16_t h0 = bfb(f0), h1 = bfb(f1);
    float r0 = f0 - __uint_as_float((uint32_t)h0 << 16);   // exact
    float r1 = f1 - __uint_as_float((uint32_t)h1 << 16);
    uint16_t l0 = bfb(r0), l1 = bfb(r1);
    ph = ((uint32_t)h1 << 16) | h0;
    pl = ((uint32_t)l1 << 16) | l0;
}
__device__ __forceinline__ void mma_bf16(float* c, const uint32_t* a,
                                         uint32_t b0, uint32_t b1) {
    asm volatile(
        "mma.sync.aligned.m16n8k16.row.col.f32.bf16.bf16.f32 "
        "{%0,%1,%2,%3}, {%4,%5,%6,%7}, {%8,%9}, {%0,%1,%2,%3};\n"
        : "+f"(c[0]), "+f"(c[1]), "+f"(c[2]), "+f"(c[3])
        : "r"(a[0]), "r"(a[1]), "r"(a[2]), "r"(a[3]), "r"(b0), "r"(b1));
}
__device__ __forceinline__ void cp_async16(uint32_t dst_smem, const void* src) {
    asm volatile("cp.async.cg.shared.global [%0], [%1], 16;\n"
                 :: "r"(dst_smem), "l"(src));
}

// ---------------------------------------------------------------------------
// packed f32x2 helpers (attn kernel)
// ---------------------------------------------------------------------------
typedef unsigned long long u64;
__device__ __forceinline__ u64 pk2(float x, float y) {
    u64 r; asm("mov.b64 %0, {%1, %2};" : "=l"(r) : "f"(x), "f"(y)); return r;
}
__device__ __forceinline__ void up2(u64 v, float& x, float& y) {
    asm("mov.b64 {%0, %1}, %2;" : "=f"(x), "=f"(y) : "l"(v));
}
__device__ __forceinline__ u64 fma2(u64 a, u64 b, u64 c) {
    u64 d; asm("fma.rn.f32x2 %0, %1, %2, %3;" : "=l"(d) : "l"(a), "l"(b), "l"(c));
    return d;
}

// ---------------------------------------------------------------------------
// bf16x3 tensor-core GEMM: C[p][o] = sum_k X[p][k] * W[o][k]
// BM=128 pix, BN=128 out, BK=32 (2 k-steps of 16). 8 warps: 4(m) x 2(n).
// X raw f32 in smem (cp.async), split to packed bf16 at fragment load.
// W pre-split hi/lo packed bf16 pairs in smem.
// XMODE 0: X global [k][p] (NCHW) -> smem k-major stride PXK
// XMODE 1: X global [p][k] (NHWC) -> smem p-major stride PX1
// YMODE 0: Y [o][p] (NCHW), YMODE 1: Y [p][o] (NHWC)
// ---------------------------------------------------------------------------
template<int XMODE, int YMODE>
__device__ __forceinline__
void mma_gemm_core(const float* __restrict__ W, const float* __restrict__ X,
                   float* __restrict__ Y, float scale)
{
    extern __shared__ uint32_t sm[];
    float*    Xs  = (float*)sm;
    uint32_t* WsH = sm + XS_CAP;
    uint32_t* WsL = sm + XS_CAP + 128 * PW2;

    const int tid   = threadIdx.x;
    const int warp  = tid >> 5;
    const int lane  = tid & 31;
    const int qid   = lane >> 2;        // 0..7
    const int qlan  = lane & 3;         // 0..3
    const int pm    = (warp & 3) * 32;  // warp m-offset
    const int on    = (warp >> 2) * 64; // warp n-offset
    const int n     = blockIdx.y;
    const int pix0  = blockIdx.x * 128;

    const float* Xn = X + (size_t)n * PLANE;
    float*       Yn = Y + (size_t)n * PLANE;

    const uint32_t xs_base = (uint32_t)__cvta_generic_to_shared(Xs);

    float acc[2][8][4];
    #pragma unroll
    for (int am = 0; am < 2; am++)
        #pragma unroll
        for (int bn = 0; bn < 8; bn++)
            #pragma unroll
            for (int j = 0; j < 4; j++) acc[am][bn][j] = 0.f;

    for (int k0 = 0; k0 < 128; k0 += 32) {
        __syncthreads();   // previous iteration's readers done

        // ---- X tile via cp.async (raw f32) ----
        if (XMODE == 0) {
            #pragma unroll
            for (int it = 0; it < 4; it++) {
                int idx = tid + it * 256;       // 0..1023
                int kk = idx >> 5, c = idx & 31;
                const float* src = Xn + (size_t)(k0 + kk) * HW + pix0 + c * 4;
                cp_async16(xs_base + (uint32_t)(kk * PXK + c * 4) * 4, src);
            }
        } else {
            #pragma unroll
            for (int it = 0; it < 4; it++) {
                int idx = tid + it * 256;
                int p = idx >> 3, c = idx & 7;
                const float* src = Xn + (size_t)(pix0 + p) * CC + k0 + c * 4;
                cp_async16(xs_base + (uint32_t)(p * PX1 + c * 4) * 4, src);
            }
        }
        asm volatile("cp.async.commit_group;\n");

        // ---- W tile: load float2, split, store packed bf16 ----
        #pragma unroll
        for (int it = 0; it < 8; it++) {
            int idx = tid + it * 256;          // 0..2047
            int o = idx >> 4, k2 = idx & 15;
            float2 wv = *(const float2*)&W[o * 128 + k0 + 2 * k2];
            uint32_t ph, pl; sp2(wv.x, wv.y, ph, pl);
            WsH[o * PW2 + k2] = ph;
            WsL[o * PW2 + k2] = pl;
        }
        asm volatile("cp.async.wait_group 0;\n");
        __syncthreads();

        // ---- compute: 2 k-steps of 16 ----
        #pragma unroll
        for (int ks = 0; ks < 2; ks++) {
            const int kb = ks * 16 + 2 * qlan;

            uint32_t aH[2][4], aL[2][4];
            #pragma unroll
            for (int am = 0; am < 2; am++) {
                const int r = pm + am * 16 + qid;
                float f0, f1, f2, f3, f4, f5, f6, f7;
                if (XMODE == 0) {
                    f0 = Xs[kb * PXK + r];           f1 = Xs[(kb + 1) * PXK + r];
                    f2 = Xs[kb * PXK + r + 8];       f3 = Xs[(kb + 1) * PXK + r + 8];
                    f4 = Xs[(kb + 8) * PXK + r];     f5 = Xs[(kb + 9) * PXK + r];
                    f6 = Xs[(kb + 8) * PXK + r + 8]; f7 = Xs[(kb + 9) * PXK + r + 8];
                } else {
                    float2 t0 = *(const float2*)&Xs[r * PX1 + kb];
                    float2 t1 = *(const float2*)&Xs[(r + 8) * PX1 + kb];
                    float2 t2 = *(const float2*)&Xs[r * PX1 + kb + 8];
                    float2 t3 = *(const float2*)&Xs[(r + 8) * PX1 + kb + 8];
                    f0 = t0.x; f1 = t0.y; f2 = t1.x; f3 = t1.y;
                    f4 = t2.x; f5 = t2.y; f6 = t3.x; f7 = t3.y;
                }
                sp2(f0, f1, aH[am][0], aL[am][0]);
                sp2(f2, f3, aH[am][1], aL[am][1]);
                sp2(f4, f5, aH[am][2], aL[am][2]);
                sp2(f6, f7, aH[am][3], aL[am][3]);
            }
            #pragma unroll
            for (int bn = 0; bn < 8; bn++) {
                int bo = (on + bn * 8 + qid) * PW2 + ks * 8 + qlan;
                uint32_t bH0 = WsH[bo], bH1 = WsH[bo + 4];
                uint32_t bL0 = WsL[bo], bL1 = WsL[bo + 4];
                #pragma unroll
                for (int am = 0; am < 2; am++) {
                    mma_bf16(acc[am][bn], aH[am], bH0, bH1);
                    mma_bf16(acc[am][bn], aH[am], bL0, bL1);
                    mma_bf16(acc[am][bn], aL[am], bH0, bH1);
                }
            }
        }
    }

    // ---- epilogue (same C-fragment layout as m16n8k8) ----
    if (YMODE == 1) {
        #pragma unroll
        for (int am = 0; am < 2; am++) {
            int p0 = pix0 + pm + am * 16 + qid;
            #pragma unroll
            for (int bn = 0; bn < 8; bn++) {
                int o = on + bn * 8 + 2 * qlan;
                float2 v0 = make_float2(acc[am][bn][0] * scale,
                                        acc[am][bn][1] * scale);
                float2 v1 = make_float2(acc[am][bn][2] * scale,
                                        acc[am][bn][3] * scale);
                *(float2*)&Yn[(size_t)p0 * CC + o]       = v0;
                *(float2*)&Yn[(size_t)(p0 + 8) * CC + o] = v1;
            }
        }
    } else {
        #pragma unroll
        for (int am = 0; am < 2; am++) {
            int p0 = pix0 + pm + am * 16 + qid;
            #pragma unroll
            for (int bn = 0; bn < 8; bn++) {
                int o = on + bn * 8 + 2 * qlan;
                Yn[(size_t)o * HW + p0]           = acc[am][bn][0] * scale;
                Yn[(size_t)(o + 1) * HW + p0]     = acc[am][bn][1] * scale;
                Yn[(size_t)o * HW + p0 + 8]       = acc[am][bn][2] * scale;
                Yn[(size_t)(o + 1) * HW + p0 + 8] = acc[am][bn][3] * scale;
            }
        }
    }
}

// Fused q/k/v projections: blockIdx.z selects which GEMM
__global__ __launch_bounds__(256, 2)
void gemm_qkv(const float* __restrict__ Wq, const float* __restrict__ Wk,
              const float* __restrict__ Wv,
              const float* __restrict__ q, const float* __restrict__ k,
              const float* __restrict__ v,
              float* __restrict__ qp, float* __restrict__ kp,
              float* __restrict__ vp, float qscale)
{
    const float* W; const float* X; float* Y; float s;
    if (blockIdx.z == 0)      { W = Wq; X = q; Y = qp; s = qscale; }
    else if (blockIdx.z == 1) { W = Wk; X = k; Y = kp; s = 1.f; }
    else                      { W = Wv; X = v; Y = vp; s = 1.f; }
    mma_gemm_core<0, 1>(W, X, Y, s);
}

__global__ __launch_bounds__(256, 2)
void gemm_out(const float* __restrict__ W, const float* __restrict__ X,
              float* __restrict__ Y)
{
    mma_gemm_core<1, 0>(W, X, Y, 1.f);
}

// ---------------------------------------------------------------------------
// Attention: one warp per pixel, lane = 4-channel group (float4).
// 25 taps share fractional weights => collapse onto a 6x6 corner grid.
// All lerp/dot/accumulate chains use packed fma.rn.f32x2 (2x FMA throughput).
// ---------------------------------------------------------------------------
__global__ __launch_bounds__(128)
void attn_kernel(const float* __restrict__ qp, const float* __restrict__ kp,
                 const float* __restrict__ vp, const float* __restrict__ flow,
                 float* __restrict__ attn_out, float* __restrict__ opre)
{
    const int warp = threadIdx.x >> 5;
    const int lane = threadIdx.x & 31;
    const int pix  = blockIdx.x * 4 + warp;
    const int n    = pix >> 12;
    const int yx   = pix & 4095;
    const int y    = yx >> 6;
    const int x    = yx & 63;
    const int head = lane >> 3;

    __shared__ float s_part[4][32][27];
    __shared__ float s_attn[4][NHEAD][K2];

    const float fx = flow[(size_t)(n * 2 + 0) * HW + yx];
    const float fy = flow[(size_t)(n * 2 + 1) * HW + yx];
    float vxn = 2.0f * ((float)x + fx) / 63.0f - 1.0f;
    float vyn = 2.0f * ((float)y + fy) / 63.0f - 1.0f;
    float xs = (vxn + 1.0f) * 0.5f * 63.0f;
    float ys = (vyn + 1.0f) * 0.5f * 63.0f;
    float bxf = floorf(xs), byf = floorf(ys);
    const float wx = xs - bxf;
    const float wy = ys - byf;
    const int ibx = (int)bxf - 2;
    const int iby = (int)byf - 2;

    unsigned mx = 0, my = 0;
    #pragma unroll
    for (int i = 0; i < 6; i++) {
        if ((unsigned)(ibx + i) <= 63u) mx |= 1u << i;
        if ((unsigned)(iby + i) <= 63u) my |= 1u << i;
    }

    const u64 wx2  = pk2(wx, wx),  nwx2 = pk2(-wx, -wx);
    const u64 wy2  = pk2(wy, wy),  nwy2 = pk2(-wy, -wy);

    const float4 q4 = *(const float4*)&qp[(size_t)pix * CC + lane * 4];
    const u64 q01 = pk2(q4.x, q4.y);
    const u64 q23 = pk2(q4.z, q4.w);

    const long long rowstride = (long long)WW * CC;
    const long long base0 = ((long long)(n << 12) + (long long)iby * WW + ibx) * CC
                          + lane * 4;

    // ================= K phase: logits =================
    {
        u64 Ha[5][2], Hb[5][2];
        #pragma unroll
        for (int jc = 0; jc < 6; jc++) {
            const float* rowp = kp + base0 + jc * rowstride;
            const bool rowok = (my >> jc) & 1;
            float4 c[6];
            #pragma unroll
            for (int i = 0; i < 6; i++) {
                c[i] = make_float4(0.f, 0.f, 0.f, 0.f);
                if (rowok && ((mx >> i) & 1))
                    c[i] = *(const float4*)(rowp + i * CC);
            }
            u64 cp2[6][2];
            #pragma unroll
            for (int i = 0; i < 6; i++) {
                cp2[i][0] = pk2(c[i].x, c[i].y);
                cp2[i][1] = pk2(c[i].z, c[i].w);
            }
            u64 (*Hc)[2] = (jc & 1) ? Hb : Ha;
            u64 (*Hp)[2] = (jc & 1) ? Ha : Hb;
            #pragma unroll
            for (int i = 0; i < 5; i++) {
                // H = (1-wx)*c0 + wx*c1  via two packed fmas
                Hc[i][0] = fma2(wx2, cp2[i+1][0], fma2(nwx2, cp2[i][0], cp2[i][0]));
                Hc[i][1] = fma2(wx2, cp2[i+1][1], fma2(nwx2, cp2[i][1], cp2[i][1]));
            }
            if (jc > 0) {
                #pragma unroll
                for (int i = 0; i < 5; i++) {
                    u64 t0 = fma2(wy2, Hc[i][0], fma2(nwy2, Hp[i][0], Hp[i][0]));
                    u64 t1 = fma2(wy2, Hc[i][1], fma2(nwy2, Hp[i][1], Hp[i][1]));
                    u64 d2 = fma2(q01, t0, fma2(q23, t1, 0ull));
                    float dx, dy; up2(d2, dx, dy);
                    s_part[warp][lane][(jc - 1) * 5 + i] = dx + dy;
                }
            }
        }
    }
    __syncwarp();

    const int kkl = (lane < K2) ? lane : 0;
    float hsum[4] = {0.f, 0.f, 0.f, 0.f};
    #pragma unroll
    for (int l = 0; l < 32; l++)
        hsum[l >> 3] += s_part[warp][l][kkl];

    float aout[4];
    #pragma unroll
    for (int h = 0; h < 4; h++) {
        float lg = (lane < K2) ? hsum[h] : -INFINITY;
        float m = lg;
        #pragma unroll
        for (int off = 16; off; off >>= 1)
            m = fmaxf(m, __shfl_xor_sync(0xffffffffu, m, off));
        float e = (lane < K2) ? __expf(lg - m) : 0.f;
        float s = e;
        #pragma unroll
        for (int off = 16; off; off >>= 1)
            s += __shfl_xor_sync(0xffffffffu, s, off);
        aout[h] = e / s;
    }
    if (lane < K2) {
        #pragma unroll
        for (int h = 0; h < 4; h++) {
            s_attn[warp][h][lane] = aout[h];
            attn_out[(size_t)((n * NHEAD + h) * K2 + lane) * HW + yx] = aout[h];
        }
    }
    __syncwarp();

    // ================= V phase =================
    u64 o01 = 0ull, o23 = 0ull;
    {
        u64 Ha[5][2], Hb[5][2];
        #pragma unroll
        for (int jc = 0; jc < 6; jc++) {
            const float* rowp = vp + base0 + jc * rowstride;
            const bool rowok = (my >> jc) & 1;
            float4 c[6];
            #pragma unroll
            for (int i = 0; i < 6; i++) {
                c[i] = make_float4(0.f, 0.f, 0.f, 0.f);
                if (rowok && ((mx >> i) & 1))
                    c[i] = *(const float4*)(rowp + i * CC);
            }
            u64 cp2[6][2];
            #pragma unroll
            for (int i = 0; i < 6; i++) {
                cp2[i][0] = pk2(c[i].x, c[i].y);
                cp2[i][1] = pk2(c[i].z, c[i].w);
            }
            u64 (*Hc)[2] = (jc & 1) ? Hb : Ha;
            u64 (*Hp)[2] = (jc & 1) ? Ha : Hb;
            #pragma unroll
            for (int i = 0; i < 5; i++) {
                Hc[i][0] = fma2(wx2, cp2[i+1][0], fma2(nwx2, cp2[i][0], cp2[i][0]));
                Hc[i][1] = fma2(wx2, cp2[i+1][1], fma2(nwx2, cp2[i][1], cp2[i][1]));
            }
            if (jc > 0) {
                #pragma unroll
                for (int i = 0; i < 5; i++) {
                    float aw = s_attn[warp][head][(jc - 1) * 5 + i];
                    u64 aw2 = pk2(aw, aw);
                    u64 t0 = fma2(wy2, Hc[i][0], fma2(nwy2, Hp[i][0], Hp[i][0]));
                    u64 t1 = fma2(wy2, Hc[i][1], fma2(nwy2, Hp[i][1], Hp[i][1]));
                    o01 = fma2(aw2, t0, o01);
                    o23 = fma2(aw2, t1, o23);
                }
            }
        }
    }
    float4 out4;
    up2(o01, out4.x, out4.y);
    up2(o23, out4.z, out4.w);
    *(float4*)&opre[(size_t)pix * CC + lane * 4] = out4;
}

// ---------------------------------------------------------------------------
extern "C" void kernel_launch(void* const* d_in, const int* in_sizes, int n_in,
                              void* d_out, int out_size)
{
    const float* q    = (const float*)d_in[0];
    const float* k    = (const float*)d_in[1];
    const float* v    = (const float*)d_in[2];
    const float* flow = (const float*)d_in[3];
    const float* Wq   = (const float*)d_in[4];
    const float* Wk   = (const float*)d_in[5];
    const float* Wv   = (const float*)d_in[6];
    const float* Wfc  = (const float*)d_in[7];

    float* out  = (float*)d_out;
    float* attn = out + (size_t)NB * CC * HW;

    float *qp, *kp, *vp, *opre;
    cudaGetSymbolAddress((void**)&qp,   g_qp);
    cudaGetSymbolAddress((void**)&kp,   g_kp);
    cudaGetSymbolAddress((void**)&vp,   g_vp);
    cudaGetSymbolAddress((void**)&opre, g_opre);

    const size_t smem_bytes = SMEM_U32 * sizeof(uint32_t);   // 40960
    cudaFuncSetAttribute(gemm_qkv, cudaFuncAttributeMaxDynamicSharedMemorySize,
                         (int)smem_bytes);
    cudaFuncSetAttribute(gemm_out, cudaFuncAttributeMaxDynamicSharedMemorySize,
                         (int)smem_bytes);

    const float qscale = 0.17677669529663687f;  // 1/sqrt(32)

    dim3 gqkv(HW / 128, NB, 3);
    gemm_qkv<<<gqkv, 256, smem_bytes>>>(Wq, Wk, Wv, q, k, v, qp, kp, vp, qscale);

    attn_kernel<<<NPIX / 4, 128>>>(qp, kp, vp, flow, attn, opre);

    dim3 gg(HW / 128, NB);
    gemm_out<<<gg, 256, smem_bytes>>>(Wfc, opre, out);
}

// round 6
// speedup vs baseline: 3.0910x; 1.0654x over previous
#include <cuda_runtime.h>
#include <cuda_bf16.h>
#include <math.h>
#include <stdint.h>

// ---------------------------------------------------------------------------
// n=4, C=128, H=W=64, K_SIZE=5 (K2=25), N_HEAD=4, d=32
// Inputs: q, k, v, flow, Wq, Wk, Wv, Wfc
// Output: concat( out[4,128,64,64], attn[4,4,25,64,64] )
// ---------------------------------------------------------------------------

#define NB      4
#define CC      128
#define WW      64
#define HW      4096
#define NPIX    (NB*HW)
#define PLANE   (CC*HW)
#define K2      25
#define NHEAD   4

// GEMM smem layout (u32 units), double buffered
#define PXK     132                 // X k-major row stride (528B, 16B-mult)
#define PX1     40                  // X p-major row stride (160B)
#define PW2     20                  // W packed-bf16 row stride (80B)
#define XS_STG  5120                // X stage capacity (max of 32*132=4224, 128*40=5120)
#define WH_OFF  5120                // WsH offset within stage
#define WL_OFF  7680                // WsL offset within stage (5120+2560)
#define STAGE_U32 10240             // per-stage total (5120 + 2*2560)
#define SMEM_U32 (2*STAGE_U32)      // 20480 u32 = 81920 B

#define WSZ     8192                // per-weight pre-split plane (128 o x 64 k2)

__device__ float g_qp[NB*HW*CC];    // NHWC, pre-scaled by 1/sqrt(d)
__device__ float g_kp[NB*HW*CC];    // NHWC
__device__ float g_vp[NB*HW*CC];    // NHWC
__device__ float g_opre[NB*HW*CC];  // NHWC
__device__ uint32_t g_wH[4*WSZ];    // packed bf16 hi pairs: [w][o][k2]
__device__ uint32_t g_wL[4*WSZ];    // packed bf16 lo pairs

// ---------------------------------------------------------------------------
// bf16x3 helpers
// ---------------------------------------------------------------------------
__device__ __forceinline__ uint16_t bfb(float f) {
    __nv_bfloat16 h = __float2bfloat16_rn(f);
    return *reinterpret_cast<uint16_t*>(&h);
}
__device__ __forceinline__ void sp2(float f0, float f1, uint32_t& ph, uint32_t& pl) {
    uint16_t h0 = bfb(f0), h1 = bfb(f1);
    float r0 = f0 - __uint_as_float((uint32_t)h0 << 16);   // exact
    float r1 = f1 - __uint_as_float((uint32_t)h1 << 16);
    uint16_t l0 = bfb(r0), l1 = bfb(r1);
    ph = ((uint32_t)h1 << 16) | h0;
    pl = ((uint32_t)l1 << 16) | l0;
}
__device__ __forceinline__ void mma_bf16(float* c, const uint32_t* a,
                                         uint32_t b0, uint32_t b1) {
    asm volatile(
        "mma.sync.aligned.m16n8k16.row.col.f32.bf16.bf16.f32 "
        "{%0,%1,%2,%3}, {%4,%5,%6,%7}, {%8,%9}, {%0,%1,%2,%3};\n"
        : "+f"(c[0]), "+f"(c[1]), "+f"(c[2]), "+f"(c[3])
        : "r"(a[0]), "r"(a[1]), "r"(a[2]), "r"(a[3]), "r"(b0), "r"(b1));
}
__device__ __forceinline__ void cp_async16(uint32_t dst_smem, const void* src) {
    asm volatile("cp.async.cg.shared.global [%0], [%1], 16;\n"
                 :: "r"(dst_smem), "l"(src));
}

// ---------------------------------------------------------------------------
// packed f32x2 helpers (attn kernel)
// ---------------------------------------------------------------------------
typedef unsigned long long u64;
__device__ __forceinline__ u64 pk2(float x, float y) {
    u64 r; asm("mov.b64 %0, {%1, %2};" : "=l"(r) : "f"(x), "f"(y)); return r;
}
__device__ __forceinline__ void up2(u64 v, float& x, float& y) {
    asm("mov.b64 {%0, %1}, %2;" : "=f"(x), "=f"(y) : "l"(v));
}
__device__ __forceinline__ u64 fma2(u64 a, u64 b, u64 c) {
    u64 d; asm("fma.rn.f32x2 %0, %1, %2, %3;" : "=l"(d) : "l"(a), "l"(b), "l"(c));
    return d;
}

// ---------------------------------------------------------------------------
// Pre-split all 4 weight matrices into packed bf16 hi/lo planes.
// grid (4, 4) x 256 threads: blockIdx.y = which W; 8192 float2 per W.
// ---------------------------------------------------------------------------
__global__ __launch_bounds__(256)
void presplit_w(const float* __restrict__ Wq, const float* __restrict__ Wk,
                const float* __restrict__ Wv, const float* __restrict__ Wfc)
{
    const int w = blockIdx.y;
    const float* W = (w == 0) ? Wq : (w == 1) ? Wk : (w == 2) ? Wv : Wfc;
    uint32_t* H = g_wH + w * WSZ;
    uint32_t* L = g_wL + w * WSZ;
    int base = blockIdx.x * 2048 + threadIdx.x;
    #pragma unroll
    for (int it = 0; it < 8; it++) {
        int idx = base + it * 256;              // 0..8191
        float2 wv = *(const float2*)&W[idx * 2];
        uint32_t ph, pl; sp2(wv.x, wv.y, ph, pl);
        H[idx] = ph;
        L[idx] = pl;
    }
}

// ---------------------------------------------------------------------------
// bf16x3 tensor-core GEMM with 2-stage cp.async pipeline.
// C[p][o] = sum_k X[p][k] * W[o][k].  BM=128, BN=128, BK=32 (2 k16 steps).
// X raw f32 in smem, split to packed bf16 at fragment load.
// W pre-split (global) -> cp.async into smem.
// XMODE 0: X global [k][p] (NCHW); XMODE 1: X global [p][k] (NHWC)
// YMODE 0: Y [o][p] (NCHW); YMODE 1: Y [p][o] (NHWC)
// ---------------------------------------------------------------------------
template<int XMODE, int YMODE>
__device__ __forceinline__
void mma_gemm_core(const uint32_t* __restrict__ WH, const uint32_t* __restrict__ WL,
                   const float* __restrict__ X, float* __restrict__ Y, float scale)
{
    extern __shared__ uint32_t sm[];

    const int tid   = threadIdx.x;
    const int warp  = tid >> 5;
    const int lane  = tid & 31;
    const int qid   = lane >> 2;        // 0..7
    const int qlan  = lane & 3;         // 0..3
    const int pm    = (warp & 3) * 32;  // warp m-offset
    const int on    = (warp >> 2) * 64; // warp n-offset
    const int n     = blockIdx.y;
    const int pix0  = blockIdx.x * 128;

    const float* Xn = X + (size_t)n * PLANE;
    float*       Yn = Y + (size_t)n * PLANE;

    const uint32_t smb = (uint32_t)__cvta_generic_to_shared(sm);

    // per-thread precomputed load indices
    const int xk_kk = tid >> 5, xk_c = tid & 31;        // XMODE0: 1 chunk/thread + 3 more
    const int xp_p  = tid >> 3, xp_c = tid & 7;         // XMODE1
    const int w_half = tid >> 9;                        // unused (tid<256): loop covers
    (void)w_half;

    float acc[2][8][4];
    #pragma unroll
    for (int am = 0; am < 2; am++)
        #pragma unroll
        for (int bn = 0; bn < 8; bn++)
            #pragma unroll
            for (int j = 0; j < 4; j++) acc[am][bn][j] = 0.f;

    // ---- stage loader ----
    auto load_stage = [&](int kt, int s) {
        const uint32_t sb = smb + (uint32_t)(s * STAGE_U32) * 4;
        // X tile
        if (XMODE == 0) {
            #pragma unroll
            for (int it = 0; it < 4; it++) {
                int idx = tid + it * 256;
                int kk = idx >> 5, c = idx & 31;
                const float* src = Xn + (size_t)(kt * 32 + kk) * HW + pix0 + c * 4;
                cp_async16(sb + (uint32_t)(kk * PXK + c * 4) * 4, src);
            }
        } else {
            #pragma unroll
            for (int it = 0; it < 4; it++) {
                int idx = tid + it * 256;
                int p = idx >> 3, c = idx & 7;
                const float* src = Xn + (size_t)(pix0 + p) * CC + kt * 32 + c * 4;
                cp_async16(sb + (uint32_t)(p * PX1 + c * 4) * 4, src);
            }
        }
        // W tiles (hi then lo): 512 chunks each
        #pragma unroll
        for (int it = 0; it < 4; it++) {
            int idx = tid + it * 256;           // 0..1023
            int half = idx >> 9;                // 0 = hi, 1 = lo
            int r = (idx >> 2) & 127;
            int c = idx & 3;
            const uint32_t* src = (half ? WL : WH) + r * 64 + kt * 16 + c * 4;
            uint32_t dst = sb + (uint32_t)((half ? WL_OFF : WH_OFF)
                                           + r * PW2 + c * 4) * 4;
            cp_async16(dst, src);
        }
    };

    load_stage(0, 0);
    asm volatile("cp.async.commit_group;\n");

    #pragma unroll
    for (int it = 0; it < 4; it++) {
        if (it < 3) {
            load_stage(it + 1, (it + 1) & 1);
            asm volatile("cp.async.commit_group;\n");
            asm volatile("cp.async.wait_group 1;\n");
        } else {
            asm volatile("cp.async.wait_group 0;\n");
        }
        __syncthreads();

        const int s = it & 1;
        const float*    Xs  = (const float*)(sm + s * STAGE_U32);
        const uint32_t* WsH = sm + s * STAGE_U32 + WH_OFF;
        const uint32_t* WsL = sm + s * STAGE_U32 + WL_OFF;

        #pragma unroll
        for (int ks = 0; ks < 2; ks++) {
            const int kb = ks * 16 + 2 * qlan;

            uint32_t aH[2][4], aL[2][4];
            #pragma unroll
            for (int am = 0; am < 2; am++) {
                const int r = pm + am * 16 + qid;
                float f0, f1, f2, f3, f4, f5, f6, f7;
                if (XMODE == 0) {
                    f0 = Xs[kb * PXK + r];           f1 = Xs[(kb + 1) * PXK + r];
                    f2 = Xs[kb * PXK + r + 8];       f3 = Xs[(kb + 1) * PXK + r + 8];
                    f4 = Xs[(kb + 8) * PXK + r];     f5 = Xs[(kb + 9) * PXK + r];
                    f6 = Xs[(kb + 8) * PXK + r + 8]; f7 = Xs[(kb + 9) * PXK + r + 8];
                } else {
                    float2 t0 = *(const float2*)&Xs[r * PX1 + kb];
                    float2 t1 = *(const float2*)&Xs[(r + 8) * PX1 + kb];
                    float2 t2 = *(const float2*)&Xs[r * PX1 + kb + 8];
                    float2 t3 = *(const float2*)&Xs[(r + 8) * PX1 + kb + 8];
                    f0 = t0.x; f1 = t0.y; f2 = t1.x; f3 = t1.y;
                    f4 = t2.x; f5 = t2.y; f6 = t3.x; f7 = t3.y;
                }
                sp2(f0, f1, aH[am][0], aL[am][0]);
                sp2(f2, f3, aH[am][1], aL[am][1]);
                sp2(f4, f5, aH[am][2], aL[am][2]);
                sp2(f6, f7, aH[am][3], aL[am][3]);
            }
            #pragma unroll
            for (int bn = 0; bn < 8; bn++) {
                int bo = (on + bn * 8 + qid) * PW2 + ks * 8 + qlan;
                uint32_t bH0 = WsH[bo], bH1 = WsH[bo + 4];
                uint32_t bL0 = WsL[bo], bL1 = WsL[bo + 4];
                #pragma unroll
                for (int am = 0; am < 2; am++) {
                    mma_bf16(acc[am][bn], aH[am], bH0, bH1);
                    mma_bf16(acc[am][bn], aH[am], bL0, bL1);
                    mma_bf16(acc[am][bn], aL[am], bH0, bH1);
                }
            }
        }
        if (it < 3) __syncthreads();   // stage s free for overwrite next iter
    }

    // ---- epilogue ----
    if (YMODE == 1) {
        #pragma unroll
        for (int am = 0; am < 2; am++) {
            int p0 = pix0 + pm + am * 16 + qid;
            #pragma unroll
            for (int bn = 0; bn < 8; bn++) {
                int o = on + bn * 8 + 2 * qlan;
                float2 v0 = make_float2(acc[am][bn][0] * scale,
                                        acc[am][bn][1] * scale);
                float2 v1 = make_float2(acc[am][bn][2] * scale,
                                        acc[am][bn][3] * scale);
                *(float2*)&Yn[(size_t)p0 * CC + o]       = v0;
                *(float2*)&Yn[(size_t)(p0 + 8) * CC + o] = v1;
            }
        }
    } else {
        #pragma unroll
        for (int am = 0; am < 2; am++) {
            int p0 = pix0 + pm + am * 16 + qid;
            #pragma unroll
            for (int bn = 0; bn < 8; bn++) {
                int o = on + bn * 8 + 2 * qlan;
                Yn[(size_t)o * HW + p0]           = acc[am][bn][0] * scale;
                Yn[(size_t)(o + 1) * HW + p0]     = acc[am][bn][1] * scale;
                Yn[(size_t)o * HW + p0 + 8]       = acc[am][bn][2] * scale;
                Yn[(size_t)(o + 1) * HW + p0 + 8] = acc[am][bn][3] * scale;
            }
        }
    }
}

// Fused q/k/v projections: blockIdx.z selects which GEMM
__global__ __launch_bounds__(256, 2)
void gemm_qkv(const float* __restrict__ q, const float* __restrict__ k,
              const float* __restrict__ v,
              float* __restrict__ qp, float* __restrict__ kp,
              float* __restrict__ vp, float qscale)
{
    const int z = blockIdx.z;
    const float* X = (z == 0) ? q : (z == 1) ? k : v;
    float* Y       = (z == 0) ? qp : (z == 1) ? kp : vp;
    float s        = (z == 0) ? qscale : 1.f;
    mma_gemm_core<0, 1>(g_wH + z * WSZ, g_wL + z * WSZ, X, Y, s);
}

__global__ __launch_bounds__(256, 2)
void gemm_out(const float* __restrict__ X, float* __restrict__ Y)
{
    mma_gemm_core<1, 0>(g_wH + 3 * WSZ, g_wL + 3 * WSZ, X, Y, 1.f);
}

// ---------------------------------------------------------------------------
// Attention: one warp per pixel, lane = 4-channel group (float4).
// 25 taps share fractional weights => collapse onto a 6x6 corner grid.
// Packed fma.rn.f32x2 throughout.
// ---------------------------------------------------------------------------
__global__ __launch_bounds__(128)
void attn_kernel(const float* __restrict__ qp, const float* __restrict__ kp,
                 const float* __restrict__ vp, const float* __restrict__ flow,
                 float* __restrict__ attn_out, float* __restrict__ opre)
{
    const int warp = threadIdx.x >> 5;
    const int lane = threadIdx.x & 31;
    const int pix  = blockIdx.x * 4 + warp;
    const int n    = pix >> 12;
    const int yx   = pix & 4095;
    const int y    = yx >> 6;
    const int x    = yx & 63;
    const int head = lane >> 3;

    __shared__ float s_part[4][32][27];
    __shared__ float s_attn[4][NHEAD][K2];

    const float fx = flow[(size_t)(n * 2 + 0) * HW + yx];
    const float fy = flow[(size_t)(n * 2 + 1) * HW + yx];
    float vxn = 2.0f * ((float)x + fx) / 63.0f - 1.0f;
    float vyn = 2.0f * ((float)y + fy) / 63.0f - 1.0f;
    float xs = (vxn + 1.0f) * 0.5f * 63.0f;
    float ys = (vyn + 1.0f) * 0.5f * 63.0f;
    float bxf = floorf(xs), byf = floorf(ys);
    const float wx = xs - bxf;
    const float wy = ys - byf;
    const int ibx = (int)bxf - 2;
    const int iby = (int)byf - 2;

    unsigned mx = 0, my = 0;
    #pragma unroll
    for (int i = 0; i < 6; i++) {
        if ((unsigned)(ibx + i) <= 63u) mx |= 1u << i;
        if ((unsigned)(iby + i) <= 63u) my |= 1u << i;
    }

    const u64 wx2  = pk2(wx, wx),  nwx2 = pk2(-wx, -wx);
    const u64 wy2  = pk2(wy, wy),  nwy2 = pk2(-wy, -wy);

    const float4 q4 = *(const float4*)&qp[(size_t)pix * CC + lane * 4];
    const u64 q01 = pk2(q4.x, q4.y);
    const u64 q23 = pk2(q4.z, q4.w);

    const long long rowstride = (long long)WW * CC;
    const long long base0 = ((long long)(n << 12) + (long long)iby * WW + ibx) * CC
                          + lane * 4;

    // ================= K phase: logits =================
    {
        u64 Ha[5][2], Hb[5][2];
        #pragma unroll
        for (int jc = 0; jc < 6; jc++) {
            const float* rowp = kp + base0 + jc * rowstride;
            const bool rowok = (my >> jc) & 1;
            float4 c[6];
            #pragma unroll
            for (int i = 0; i < 6; i++) {
                c[i] = make_float4(0.f, 0.f, 0.f, 0.f);
                if (rowok && ((mx >> i) & 1))
                    c[i] = *(const float4*)(rowp + i * CC);
            }
            u64 cp2[6][2];
            #pragma unroll
            for (int i = 0; i < 6; i++) {
                cp2[i][0] = pk2(c[i].x, c[i].y);
                cp2[i][1] = pk2(c[i].z, c[i].w);
            }
            u64 (*Hc)[2] = (jc & 1) ? Hb : Ha;
            u64 (*Hp)[2] = (jc & 1) ? Ha : Hb;
            #pragma unroll
            for (int i = 0; i < 5; i++) {
                Hc[i][0] = fma2(wx2, cp2[i+1][0], fma2(nwx2, cp2[i][0], cp2[i][0]));
                Hc[i][1] = fma2(wx2, cp2[i+1][1], fma2(nwx2, cp2[i][1], cp2[i][1]));
            }
            if (jc > 0) {
                #pragma unroll
                for (int i = 0; i < 5; i++) {
                    u64 t0 = fma2(wy2, Hc[i][0], fma2(nwy2, Hp[i][0], Hp[i][0]));
                    u64 t1 = fma2(wy2, Hc[i][1], fma2(nwy2, Hp[i][1], Hp[i][1]));
                    u64 d2 = fma2(q01, t0, fma2(q23, t1, 0ull));
                    float dx, dy; up2(d2, dx, dy);
                    s_part[warp][lane][(jc - 1) * 5 + i] = dx + dy;
                }
            }
        }
    }
    __syncwarp();

    const int kkl = (lane < K2) ? lane : 0;
    float hsum[4] = {0.f, 0.f, 0.f, 0.f};
    #pragma unroll
    for (int l = 0; l < 32; l++)
        hsum[l >> 3] += s_part[warp][l][kkl];

    float aout[4];
    #pragma unroll
    for (int h = 0; h < 4; h++) {
        float lg = (lane < K2) ? hsum[h] : -INFINITY;
        float m = lg;
        #pragma unroll
        for (int off = 16; off; off >>= 1)
            m = fmaxf(m, __shfl_xor_sync(0xffffffffu, m, off));
        float e = (lane < K2) ? __expf(lg - m) : 0.f;
        float s = e;
        #pragma unroll
        for (int off = 16; off; off >>= 1)
            s += __shfl_xor_sync(0xffffffffu, s, off);
        aout[h] = e / s;
    }
    if (lane < K2) {
        #pragma unroll
        for (int h = 0; h < 4; h++) {
            s_attn[warp][h][lane] = aout[h];
            attn_out[(size_t)((n * NHEAD + h) * K2 + lane) * HW + yx] = aout[h];
        }
    }
    __syncwarp();

    // ================= V phase =================
    u64 o01 = 0ull, o23 = 0ull;
    {
        u64 Ha[5][2], Hb[5][2];
        #pragma unroll
        for (int jc = 0; jc < 6; jc++) {
            const float* rowp = vp + base0 + jc * rowstride;
            const bool rowok = (my >> jc) & 1;
            float4 c[6];
            #pragma unroll
            for (int i = 0; i < 6; i++) {
                c[i] = make_float4(0.f, 0.f, 0.f, 0.f);
                if (rowok && ((mx >> i) & 1))
                    c[i] = *(const float4*)(rowp + i * CC);
            }
            u64 cp2[6][2];
            #pragma unroll
            for (int i = 0; i < 6; i++) {
                cp2[i][0] = pk2(c[i].x, c[i].y);
                cp2[i][1] = pk2(c[i].z, c[i].w);
            }
            u64 (*Hc)[2] = (jc & 1) ? Hb : Ha;
            u64 (*Hp)[2] = (jc & 1) ? Ha : Hb;
            #pragma unroll
            for (int i = 0; i < 5; i++) {
                Hc[i][0] = fma2(wx2, cp2[i+1][0], fma2(nwx2, cp2[i][0], cp2[i][0]));
                Hc[i][1] = fma2(wx2, cp2[i+1][1], fma2(nwx2, cp2[i][1], cp2[i][1]));
            }
            if (jc > 0) {
                #pragma unroll
                for (int i = 0; i < 5; i++) {
                    float aw = s_attn[warp][head][(jc - 1) * 5 + i];
                    u64 aw2 = pk2(aw, aw);
                    u64 t0 = fma2(wy2, Hc[i][0], fma2(nwy2, Hp[i][0], Hp[i][0]));
                    u64 t1 = fma2(wy2, Hc[i][1], fma2(nwy2, Hp[i][1], Hp[i][1]));
                    o01 = fma2(aw2, t0, o01);
                    o23 = fma2(aw2, t1, o23);
                }
            }
        }
    }
    float4 out4;
    up2(o01, out4.x, out4.y);
    up2(o23, out4.z, out4.w);
    *(float4*)&opre[(size_t)pix * CC + lane * 4] = out4;
}

// ---------------------------------------------------------------------------
extern "C" void kernel_launch(void* const* d_in, const int* in_sizes, int n_in,
                              void* d_out, int out_size)
{
    const float* q    = (const float*)d_in[0];
    const float* k    = (const float*)d_in[1];
    const float* v    = (const float*)d_in[2];
    const float* flow = (const float*)d_in[3];
    const float* Wq   = (const float*)d_in[4];
    const float* Wk   = (const float*)d_in[5];
    const float* Wv   = (const float*)d_in[6];
    const float* Wfc  = (const float*)d_in[7];

    float* out  = (float*)d_out;
    float* attn = out + (size_t)NB * CC * HW;

    float *qp, *kp, *vp, *opre;
    cudaGetSymbolAddress((void**)&qp,   g_qp);
    cudaGetSymbolAddress((void**)&kp,   g_kp);
    cudaGetSymbolAddress((void**)&vp,   g_vp);
    cudaGetSymbolAddress((void**)&opre, g_opre);

    const size_t smem_bytes = SMEM_U32 * sizeof(uint32_t);   // 81920
    cudaFuncSetAttribute(gemm_qkv, cudaFuncAttributeMaxDynamicSharedMemorySize,
                         (int)smem_bytes);
    cudaFuncSetAttribute(gemm_out, cudaFuncAttributeMaxDynamicSharedMemorySize,
                         (int)smem_bytes);

    const float qscale = 0.17677669529663687f;  // 1/sqrt(32)

    dim3 gps(4, 4);
    presplit_w<<<gps, 256>>>(Wq, Wk, Wv, Wfc);

    dim3 gqkv(HW / 128, NB, 3);
    gemm_qkv<<<gqkv, 256, smem_bytes>>>(q, k, v, qp, kp, vp, qscale);

    attn_kernel<<<NPIX / 4, 128>>>(qp, kp, vp, flow, attn, opre);

    dim3 gg(HW / 128, NB);
    gemm_out<<<gg, 256, smem_bytes>>>(opre, out);
}